// round 10
// baseline (speedup 1.0000x reference)
#include <cuda_runtime.h>
#include <cuda_fp16.h>
#include <stdint.h>
#include <math.h>

#define ASTR 40            /* padded smem stride in fp16 elems (80B rows) */
#define BK 32
#define NITER 16           /* K=512 / BK */
#define STAGES 4
#define KSPLIT 64
#define KCHUNK 4096
#define BN_LD 136          /* final kernel B smem stride ([k][n] layout) */

/* Scratch: __device__ globals (allocation-free rule) */
__device__ uint16_t xd16[32 * 512 * 512];   /* x direct fp16 [b*512+n][h] */
__device__ uint16_t xt16[32 * 512 * 512];   /* x^T fp16 [b][h][m] */
__device__ uint16_t wt16[2 * 512 * 512];    /* Wq^T, Wk^T fp16 [z][n][k] */
__device__ uint16_t q16[32 * 512 * 512];    /* q fp16 */
__device__ uint16_t k16[32 * 512 * 512];    /* k fp16 */
__device__ uint16_t at16[32 * 512 * 512];   /* exp(sigmoid(scores)) fp16 */
__device__ uint16_t ax16[32 * 512 * 512];   /* softmax @ x, fp16 */
__device__ float g_rinv[32 * 512];          /* per-row 1/sum(exp) */
__device__ float g_part[KSPLIT * 32 * 512];

/* ------------------------------------------------------------------ */
/* Helpers                                                             */
/* ------------------------------------------------------------------ */
__device__ __forceinline__ uint32_t sptr(const void* p) {
    return (uint32_t)__cvta_generic_to_shared(p);
}

__device__ __forceinline__ void ldsm_x4(uint32_t& r0, uint32_t& r1,
                                        uint32_t& r2, uint32_t& r3,
                                        uint32_t addr) {
    asm volatile("ldmatrix.sync.aligned.m8n8.x4.shared.b16 {%0,%1,%2,%3}, [%4];"
                 : "=r"(r0), "=r"(r1), "=r"(r2), "=r"(r3)
                 : "r"(addr));
}

__device__ __forceinline__ void ldsm_x4_trans(uint32_t& r0, uint32_t& r1,
                                              uint32_t& r2, uint32_t& r3,
                                              uint32_t addr) {
    asm volatile("ldmatrix.sync.aligned.m8n8.x4.trans.shared.b16 {%0,%1,%2,%3}, [%4];"
                 : "=r"(r0), "=r"(r1), "=r"(r2), "=r"(r3)
                 : "r"(addr));
}

__device__ __forceinline__ void mma_f16(float* c, const uint32_t* a,
                                        const uint32_t* b) {
    asm volatile(
        "mma.sync.aligned.m16n8k16.row.col.f32.f16.f16.f32 "
        "{%0,%1,%2,%3}, {%4,%5,%6,%7}, {%8,%9}, {%0,%1,%2,%3};"
        : "+f"(c[0]), "+f"(c[1]), "+f"(c[2]), "+f"(c[3])
        : "r"(a[0]), "r"(a[1]), "r"(a[2]), "r"(a[3]),
          "r"(b[0]), "r"(b[1]));
}

__device__ __forceinline__ void cpa16(uint32_t dst, const void* src) {
    asm volatile("cp.async.cg.shared.global [%0], [%1], 16;"
                 :: "r"(dst), "l"(src) : "memory");
}
__device__ __forceinline__ void cpa_commit() {
    asm volatile("cp.async.commit_group;" ::: "memory");
}
template <int N>
__device__ __forceinline__ void cpa_wait() {
    asm volatile("cp.async.wait_group %0;" :: "n"(N) : "memory");
}

__device__ __forceinline__ uint16_t h1(float v) {
    __half h = __float2half_rn(v);
    return *reinterpret_cast<uint16_t*>(&h);
}

__device__ __forceinline__ void pack8_plain(const float* v, uint4& u) {
    uint16_t h[8];
#pragma unroll
    for (int j = 0; j < 8; j++) {
        h[j] = h1(v[j]);
    }
    u.x = (uint32_t)h[0] | ((uint32_t)h[1] << 16);
    u.y = (uint32_t)h[2] | ((uint32_t)h[3] << 16);
    u.z = (uint32_t)h[4] | ((uint32_t)h[5] << 16);
    u.w = (uint32_t)h[6] | ((uint32_t)h[7] << 16);
}

/* copy one 128x32 fp16 tile (src ld=512, pre-offset by k0) into smem  */
__device__ __forceinline__ void cpa_tile(uint32_t sdst, const uint16_t* src,
                                         int tid) {
#pragma unroll
    for (int i = 0; i < 2; i++) {
        int q = i * 256 + tid;
        int row = q >> 2;
        int c = (q & 3) * 8;
        cpa16(sdst + (uint32_t)(row * ASTR + c) * 2, src + (size_t)row * 512 + c);
    }
}

/* ------------------------------------------------------------------ */
/* Compute: one BK=32 slab, 128x128 CTA tile. All B fragments for the  */
/* whole slab hoisted up front to widen the LSU/MMA overlap window.    */
/* ------------------------------------------------------------------ */
__device__ __forceinline__ void compute128_h(uint32_t sA, uint32_t sB,
                                             int wm, int wn, int lane,
                                             float acc[4][4][4]) {
    const int lr = (lane & 7) + ((lane >> 3) & 1) * 8;
    const int lc = (lane >> 4) * 8;

    uint32_t b[2][4][2];    /* [ks-half][nt][frag] */
#pragma unroll
    for (int h = 0; h < 2; h++) {
#pragma unroll
        for (int p = 0; p < 2; p++) {
            uint32_t off = (uint32_t)(((wn * 32 + p * 16 + lr) * ASTR + h * 16 + lc) * 2);
            uint32_t r0, r1, r2, r3;
            ldsm_x4(r0, r1, r2, r3, sB + off);
            b[h][2 * p][0] = r0;
            b[h][2 * p][1] = r2;
            b[h][2 * p + 1][0] = r1;
            b[h][2 * p + 1][1] = r3;
        }
    }
#pragma unroll
    for (int h = 0; h < 2; h++) {
        uint32_t a[4][4];
#pragma unroll
        for (int mt = 0; mt < 4; mt++) {
            uint32_t off = (uint32_t)(((wm * 64 + mt * 16 + lr) * ASTR + h * 16 + lc) * 2);
            ldsm_x4(a[mt][0], a[mt][1], a[mt][2], a[mt][3], sA + off);
        }
#pragma unroll
        for (int mt = 0; mt < 4; mt++) {
#pragma unroll
            for (int nt = 0; nt < 4; nt++) {
                mma_f16(acc[mt][nt], a[mt], b[h][nt]);
            }
        }
    }
}

/* ------------------------------------------------------------------ */
/* Prep 1: x -> direct fp16 (xd16) AND transposed fp16 (xt16).         */
/* ------------------------------------------------------------------ */
__global__ __launch_bounds__(256) void prep_x(const float* __restrict__ x) {
    __shared__ float ts[64][65];
    const int tid = threadIdx.x;
    const int m0 = blockIdx.y * 64;
    const int h0 = blockIdx.x * 64;
    const size_t off = (size_t)blockIdx.z * 262144;
    const float* src = x + off + (size_t)m0 * 512 + h0;

#pragma unroll
    for (int i = 0; i < 4; i++) {
        int lin = i * 256 + tid;
        int r = lin >> 4;
        int c4 = (lin & 15) * 4;
        float4 v = *(const float4*)(src + (size_t)r * 512 + c4);
        ts[r][c4 + 0] = v.x;
        ts[r][c4 + 1] = v.y;
        ts[r][c4 + 2] = v.z;
        ts[r][c4 + 3] = v.w;
    }
    __syncthreads();

#pragma unroll
    for (int i = 0; i < 2; i++) {
        int lin = i * 256 + tid;
        int r = lin >> 3;
        int c8 = (lin & 7) * 8;
        float v[8];
#pragma unroll
        for (int j = 0; j < 8; j++) {
            v[j] = ts[r][c8 + j];
        }
        uint4 u;
        pack8_plain(v, u);
        *(uint4*)(xd16 + off + (size_t)(m0 + r) * 512 + h0 + c8) = u;
    }
#pragma unroll
    for (int i = 0; i < 2; i++) {
        int lin = i * 256 + tid;
        int hr = lin >> 3;
        int m8 = (lin & 7) * 8;
        float v[8];
#pragma unroll
        for (int j = 0; j < 8; j++) {
            v[j] = ts[m8 + j][hr];
        }
        uint4 u;
        pack8_plain(v, u);
        *(uint4*)(xt16 + off + (size_t)(h0 + hr) * 512 + m0 + m8) = u;
    }
}

/* ------------------------------------------------------------------ */
/* Prep 2: Wq/Wk -> transposed plain fp16 (wt16). grid (8,8,2).        */
/* ------------------------------------------------------------------ */
__global__ __launch_bounds__(256) void prep_wt(const float* __restrict__ Wq,
                                               const float* __restrict__ Wk) {
    __shared__ float ts[64][65];
    const int tid = threadIdx.x;
    const int k0 = blockIdx.y * 64;
    const int n0 = blockIdx.x * 64;
    const float* src = (blockIdx.z ? Wk : Wq) + (size_t)k0 * 512 + n0;
    const size_t dstoff = (size_t)blockIdx.z * 262144;

#pragma unroll
    for (int i = 0; i < 4; i++) {
        int lin = i * 256 + tid;
        int r = lin >> 4;
        int c4 = (lin & 15) * 4;
        float4 v = *(const float4*)(src + (size_t)r * 512 + c4);
        ts[r][c4 + 0] = v.x;
        ts[r][c4 + 1] = v.y;
        ts[r][c4 + 2] = v.z;
        ts[r][c4 + 3] = v.w;
    }
    __syncthreads();

#pragma unroll
    for (int i = 0; i < 2; i++) {
        int lin = i * 256 + tid;
        int nr = lin >> 3;
        int k8 = (lin & 7) * 8;
        float v[8];
#pragma unroll
        for (int j = 0; j < 8; j++) {
            v[j] = ts[k8 + j][nr];
        }
        uint4 u;
        pack8_plain(v, u);
        *(uint4*)(wt16 + dstoff + (size_t)(n0 + nr) * 512 + k0 + k8) = u;
    }
}

/* ------------------------------------------------------------------ */
/* Generic plain-fp16 GEMM body: 4-stage cp.async pipeline.            */
/* ------------------------------------------------------------------ */
#define PTILE (128 * ASTR)
#define STAGE_BYTES (2 * PTILE * 2)
#define GSMEM_BYTES (STAGES * STAGE_BYTES)   /* 81920 */

__device__ __forceinline__ void gemm128_body(
    const uint16_t* __restrict__ A, const uint16_t* __restrict__ B,
    uint32_t s0, int tid, int wm, int wn, int lane, float acc[4][4][4]) {
#pragma unroll
    for (int s = 0; s < STAGES - 1; s++) {
        uint32_t sb = s0 + s * STAGE_BYTES;
        cpa_tile(sb, A + s * BK, tid);
        cpa_tile(sb + PTILE * 2, B + s * BK, tid);
        cpa_commit();
    }

    for (int c = 0; c < NITER; c++) {
        cpa_wait<STAGES - 2>();
        __syncthreads();
        int nf = c + STAGES - 1;
        if (nf < NITER) {
            uint32_t sb = s0 + (nf & (STAGES - 1)) * STAGE_BYTES;
            cpa_tile(sb, A + nf * BK, tid);
            cpa_tile(sb + PTILE * 2, B + nf * BK, tid);
        }
        cpa_commit();   /* unconditional: keeps group count in lockstep */
        uint32_t sb = s0 + (c & (STAGES - 1)) * STAGE_BYTES;
        compute128_h(sb, sb + PTILE * 2, wm, wn, lane, acc);
    }
}

/* ------------------------------------------------------------------ */
/* Kernel: q/k projections. grid (4, 128, 2), dyn smem, 2 CTAs/SM.     */
/* ------------------------------------------------------------------ */
__global__ __launch_bounds__(256, 2) void proj_kernel(
    const float* __restrict__ bq, const float* __restrict__ bk) {
    extern __shared__ uint16_t dynsm[];

    const int tid = threadIdx.x;
    const int lane = tid & 31;
    const int wid = tid >> 5;
    const int wm = wid & 1;
    const int wn = wid >> 1;
    const int z = blockIdx.z;
    const int row0 = blockIdx.y * 128;
    const int col0 = blockIdx.x * 128;

    const uint16_t* A = xd16 + (size_t)row0 * 512;
    const uint16_t* B = wt16 + (size_t)z * 262144 + (size_t)col0 * 512;

    float acc[4][4][4] = {};
    gemm128_body(A, B, sptr(dynsm), tid, wm, wn, lane, acc);

    const float* bias = z ? bk : bq;
    uint16_t* O = z ? k16 : q16;
    const int g = lane >> 2;
    const int tg2 = (lane & 3) * 2;
#pragma unroll
    for (int mt = 0; mt < 4; mt++) {
        int r = row0 + wm * 64 + mt * 16 + g;
#pragma unroll
        for (int nt = 0; nt < 4; nt++) {
            int c = col0 + wn * 32 + nt * 8 + tg2;
            float2 bv = *(const float2*)(bias + c);
            __half2 p0 = __floats2half2_rn(acc[mt][nt][0] + bv.x, acc[mt][nt][1] + bv.y);
            __half2 p1 = __floats2half2_rn(acc[mt][nt][2] + bv.x, acc[mt][nt][3] + bv.y);
            *(uint32_t*)(O + (size_t)r * 512 + c) = *reinterpret_cast<uint32_t*>(&p0);
            *(uint32_t*)(O + (size_t)(r + 8) * 512 + c) = *reinterpret_cast<uint32_t*>(&p1);
        }
    }
}

/* ------------------------------------------------------------------ */
/* Kernel: scores -> at16 = exp(sigmoid(q k^T / sqrt(512))) fp16.      */
/* grid (4,4,32). fp32 attn is produced later by rowsum_kernel.        */
/* ------------------------------------------------------------------ */
__global__ __launch_bounds__(256, 2) void scores_kernel() {
    extern __shared__ uint16_t dynsm[];

    const int tid = threadIdx.x;
    const int lane = tid & 31;
    const int wid = tid >> 5;
    const int wm = wid & 1;
    const int wn = wid >> 1;
    const int b = blockIdx.z;
    const int row0 = blockIdx.y * 128;
    const int col0 = blockIdx.x * 128;

    const uint16_t* A = q16 + ((size_t)b * 512 + row0) * 512;
    const uint16_t* B = k16 + ((size_t)b * 512 + col0) * 512;

    float acc[4][4][4] = {};
    gemm128_body(A, B, sptr(dynsm), tid, wm, wn, lane, acc);

    const float scale = 0.04419417382415922f; /* 1/sqrt(512) */
    uint16_t* E = at16 + (size_t)b * 262144;
    const int g = lane >> 2;
    const int tg2 = (lane & 3) * 2;
#pragma unroll
    for (int mt = 0; mt < 4; mt++) {
        int r = row0 + wm * 64 + mt * 16 + g;
#pragma unroll
        for (int nt = 0; nt < 4; nt++) {
            int c = col0 + wn * 32 + nt * 8 + tg2;
            float e0 = expf(1.f / (1.f + expf(-acc[mt][nt][0] * scale)));
            float e1 = expf(1.f / (1.f + expf(-acc[mt][nt][1] * scale)));
            float e2 = expf(1.f / (1.f + expf(-acc[mt][nt][2] * scale)));
            float e3 = expf(1.f / (1.f + expf(-acc[mt][nt][3] * scale)));
            __half2 p0 = __floats2half2_rn(e0, e1);
            __half2 p1 = __floats2half2_rn(e2, e3);
            *(uint32_t*)(E + (size_t)r * 512 + c) = *reinterpret_cast<uint32_t*>(&p0);
            *(uint32_t*)(E + (size_t)(r + 8) * 512 + c) = *reinterpret_cast<uint32_t*>(&p1);
        }
    }
}

/* ------------------------------------------------------------------ */
/* Kernel: warp-per-row rowsum. Reads at16 (fp16 exp), writes          */
/* normalized fp32 attn and g_rinv. grid 2048 x 256.                   */
/* ------------------------------------------------------------------ */
__global__ __launch_bounds__(256) void rowsum_kernel(float* __restrict__ attn) {
    const int w = threadIdx.x >> 5;
    const int lane = threadIdx.x & 31;
    const size_t row = (size_t)blockIdx.x * 8 + w;
    const size_t base = row * 512;

    uint2 u[4];
#pragma unroll
    for (int i = 0; i < 4; i++) {
        u[i] = *(const uint2*)(at16 + base + i * 128 + lane * 4);
    }
    float e[16];
    float s = 0.f;
#pragma unroll
    for (int i = 0; i < 4; i++) {
        __half2 h0 = *reinterpret_cast<__half2*>(&u[i].x);
        __half2 h1v = *reinterpret_cast<__half2*>(&u[i].y);
        float2 f0 = __half22float2(h0);
        float2 f1 = __half22float2(h1v);
        e[i * 4 + 0] = f0.x;
        e[i * 4 + 1] = f0.y;
        e[i * 4 + 2] = f1.x;
        e[i * 4 + 3] = f1.y;
        s += f0.x + f0.y + f1.x + f1.y;
    }
#pragma unroll
    for (int o = 16; o > 0; o >>= 1) {
        s += __shfl_xor_sync(0xffffffffu, s, o);
    }
    const float inv = 1.f / s;
    if (lane == 0) {
        g_rinv[row] = inv;
    }
#pragma unroll
    for (int i = 0; i < 4; i++) {
        float4 o;
        o.x = e[i * 4 + 0] * inv;
        o.y = e[i * 4 + 1] * inv;
        o.z = e[i * 4 + 2] * inv;
        o.w = e[i * 4 + 3] * inv;
        *(float4*)(attn + base + i * 128 + lane * 4) = o;
    }
}

/* ------------------------------------------------------------------ */
/* Kernel: ax = softmax @ x via exp-A GEMM + per-row 1/sum epilogue.   */
/* grid (4,4,32), 2 CTAs/SM. Output fp16.                              */
/* ------------------------------------------------------------------ */
__global__ __launch_bounds__(256, 2) void ax_kernel() {
    extern __shared__ uint16_t dynsm[];

    const int tid = threadIdx.x;
    const int lane = tid & 31;
    const int wid = tid >> 5;
    const int wm = wid & 1;
    const int wn = wid >> 1;
    const int b = blockIdx.z;
    const int row0 = blockIdx.y * 128;
    const int col0 = blockIdx.x * 128;

    const uint16_t* A = at16 + ((size_t)b * 512 + row0) * 512;
    const uint16_t* B = xt16 + ((size_t)b * 512 + col0) * 512;

    float acc[4][4][4] = {};
    gemm128_body(A, B, sptr(dynsm), tid, wm, wn, lane, acc);

    const size_t rowg = (size_t)b * 512;
    const int g = lane >> 2;
    const int tg2 = (lane & 3) * 2;
#pragma unroll
    for (int mt = 0; mt < 4; mt++) {
        int r = row0 + wm * 64 + mt * 16 + g;
        float i0 = g_rinv[rowg + r];
        float i1 = g_rinv[rowg + r + 8];
#pragma unroll
        for (int nt = 0; nt < 4; nt++) {
            int c = col0 + wn * 32 + nt * 8 + tg2;
            __half2 p0 = __floats2half2_rn(acc[mt][nt][0] * i0, acc[mt][nt][1] * i0);
            __half2 p1 = __floats2half2_rn(acc[mt][nt][2] * i1, acc[mt][nt][3] * i1);
            *(uint32_t*)(ax16 + (rowg + r) * 512 + c) = *reinterpret_cast<uint32_t*>(&p0);
            *(uint32_t*)(ax16 + (rowg + r + 8) * 512 + c) = *reinterpret_cast<uint32_t*>(&p1);
        }
    }
}

/* ------------------------------------------------------------------ */
/* Kernel: split-K partials of out = ax.reshape(32,262144) @ Wm.       */
/* B in native [k][n] smem layout, ldmatrix.trans fetch. grid (4,64).  */
/* ------------------------------------------------------------------ */
#define FAEL (32 * ASTR)               /* A stage elems: [m][k] */
#define FBEL (32 * BN_LD)              /* B stage elems: [k][n] */
#define FSTAGE (FAEL + FBEL)

__global__ __launch_bounds__(256, 2) void final_kernel(const float* __restrict__ Wm) {
    __shared__ alignas(16) uint16_t dsm[2 * FSTAGE];

    const int tid = threadIdx.x;
    const int lane = tid & 31;
    const int wid = tid >> 5;
    const int col0 = blockIdx.x * 128;
    const size_t kbase = (size_t)blockIdx.y * KCHUNK;

    float acc[2][2][4] = {};
    uint2 va;
    float4 vb[4];
    const int am = tid >> 3;
    const int ak = (tid & 7) * 4;
    const int bk_r = tid >> 5;
    const int bn4 = (tid & 31) * 4;

    va = *(const uint2*)(ax16 + (size_t)am * 262144 + kbase + ak);
#pragma unroll
    for (int i = 0; i < 4; i++) {
        vb[i] = *(const float4*)(Wm + (kbase + bk_r + i * 8) * 512 + col0 + bn4);
    }

    auto store_stage = [&](uint16_t* stg) {
        *(uint2*)(stg + am * ASTR + ak) = va;
        uint16_t* bs = stg + FAEL;
#pragma unroll
        for (int i = 0; i < 4; i++) {
            __half2 p0 = __floats2half2_rn(vb[i].x, vb[i].y);
            __half2 p1 = __floats2half2_rn(vb[i].z, vb[i].w);
            uint2 u;
            u.x = *reinterpret_cast<uint32_t*>(&p0);
            u.y = *reinterpret_cast<uint32_t*>(&p1);
            *(uint2*)(bs + (bk_r + i * 8) * BN_LD + bn4) = u;
        }
    };

    store_stage(dsm);
    va = *(const uint2*)(ax16 + (size_t)am * 262144 + kbase + BK + ak);
#pragma unroll
    for (int i = 0; i < 4; i++) {
        vb[i] = *(const float4*)(Wm + (kbase + BK + bk_r + i * 8) * 512 + col0 + bn4);
    }
    __syncthreads();

    const int lr = (lane & 7) + ((lane >> 3) & 1) * 8;
    const int lc = (lane >> 4) * 8;
    const int trow = (lane >> 4) * 8 + (lane & 7);
    const int tcol = ((lane >> 3) & 1) * 8;

    for (int k0 = 0; k0 < KCHUNK; k0 += BK) {
        int cur = (k0 >> 5) & 1;
        if (k0 + BK < KCHUNK) {
            store_stage(dsm + (cur ^ 1) * FSTAGE);
        }
        if (k0 + 2 * BK < KCHUNK) {
            va = *(const uint2*)(ax16 + (size_t)am * 262144 + kbase + k0 + 2 * BK + ak);
#pragma unroll
            for (int i = 0; i < 4; i++) {
                vb[i] = *(const float4*)(Wm + (kbase + k0 + 2 * BK + bk_r + i * 8) * 512 +
                                         col0 + bn4);
            }
        }
        uint32_t base = sptr(dsm) + cur * FSTAGE * 2;
        uint32_t sA = base;
        uint32_t sB = base + FAEL * 2;
#pragma unroll
        for (int ks = 0; ks < BK; ks += 16) {
            uint32_t bf[2][2];
            uint32_t offb = (uint32_t)(((ks + trow) * BN_LD + wid * 16 + tcol) * 2);
            uint32_t r0, r1, r2, r3;
            ldsm_x4_trans(r0, r1, r2, r3, sB + offb);
            bf[0][0] = r0;
            bf[1][0] = r1;
            bf[0][1] = r2;
            bf[1][1] = r3;
            uint32_t a[2][4];
#pragma unroll
            for (int mt = 0; mt < 2; mt++) {
                uint32_t offa = (uint32_t)(((mt * 16 + lr) * ASTR + ks + lc) * 2);
                ldsm_x4(a[mt][0], a[mt][1], a[mt][2], a[mt][3], sA + offa);
            }
#pragma unroll
            for (int mt = 0; mt < 2; mt++) {
#pragma unroll
                for (int nt = 0; nt < 2; nt++) {
                    mma_f16(acc[mt][nt], a[mt], bf[nt]);
                }
            }
        }
        __syncthreads();
    }

    const int g = lane >> 2;
    const int tg2 = (lane & 3) * 2;
    float* P = g_part + (size_t)blockIdx.y * 16384;
#pragma unroll
    for (int mt = 0; mt < 2; mt++) {
        int r = mt * 16 + g;
#pragma unroll
        for (int nt = 0; nt < 2; nt++) {
            int c = col0 + wid * 16 + nt * 8 + tg2;
            float2 o0;
            float2 o1;
            o0.x = acc[mt][nt][0];
            o0.y = acc[mt][nt][1];
            o1.x = acc[mt][nt][2];
            o1.y = acc[mt][nt][3];
            *(float2*)(P + (size_t)r * 512 + c) = o0;
            *(float2*)(P + (size_t)(r + 8) * 512 + c) = o1;
        }
    }
}

/* ------------------------------------------------------------------ */
/* Kernel: deterministic split-K reduce + bias. grid 64 x 256.         */
/* ------------------------------------------------------------------ */
__global__ __launch_bounds__(256) void reduce_kernel(float* __restrict__ out,
                                                     const float* __restrict__ bm) {
    const int idx = blockIdx.x * 256 + threadIdx.x;
    const int n = idx & 511;
    float sum = bm[n];
#pragma unroll 8
    for (int s = 0; s < KSPLIT; s++) {
        sum += g_part[(size_t)s * 16384 + idx];
    }
    out[idx] = sum;
}

/* ------------------------------------------------------------------ */
extern "C" void kernel_launch(void* const* d_in, const int* in_sizes, int n_in,
                              void* d_out, int out_size) {
    const float* x = (const float*)d_in[0];
    const float* Wq = (const float*)d_in[1];
    const float* bq = (const float*)d_in[2];
    const float* Wk = (const float*)d_in[3];
    const float* bk = (const float*)d_in[4];
    const float* Wm = (const float*)d_in[5];
    const float* bm = (const float*)d_in[6];

    float* out = (float*)d_out;   /* [32, 512] */
    float* attn = out + 32 * 512; /* [32, 512, 512] */

    cudaFuncSetAttribute(proj_kernel, cudaFuncAttributeMaxDynamicSharedMemorySize,
                         GSMEM_BYTES);
    cudaFuncSetAttribute(scores_kernel, cudaFuncAttributeMaxDynamicSharedMemorySize,
                         GSMEM_BYTES);
    cudaFuncSetAttribute(ax_kernel, cudaFuncAttributeMaxDynamicSharedMemorySize,
                         GSMEM_BYTES);

    prep_x<<<dim3(8, 8, 32), 256>>>(x);
    prep_wt<<<dim3(8, 8, 2), 256>>>(Wq, Wk);
    proj_kernel<<<dim3(4, 128, 2), 256, GSMEM_BYTES>>>(bq, bk);
    scores_kernel<<<dim3(4, 4, 32), 256, GSMEM_BYTES>>>();
    rowsum_kernel<<<2048, 256>>>(attn);
    ax_kernel<<<dim3(4, 4, 32), 256, GSMEM_BYTES>>>();
    final_kernel<<<dim3(4, KSPLIT), 256>>>(Wm);
    reduce_kernel<<<64, 256>>>(out, bm);
}

// round 11
// speedup vs baseline: 1.0499x; 1.0499x over previous
#include <cuda_runtime.h>
#include <cuda_fp16.h>
#include <stdint.h>
#include <math.h>

/* GEMM-trio pipeline constants */
#define GBK 64             /* k per slab */
#define GASTR 72           /* padded smem stride (144 B rows, 16B aligned) */
#define GNITER 8           /* K=512 / GBK */
#define GSTAGES 3

/* final kernel constants */
#define FBK 32
#define FASTR 40
#define KSPLIT 64
#define KCHUNK 4096
#define BN_LD 136

/* Scratch: __device__ globals (allocation-free rule) */
__device__ uint16_t xd16[32 * 512 * 512];   /* x direct fp16 [b*512+n][h] */
__device__ uint16_t xt16[32 * 512 * 512];   /* x^T fp16 [b][h][m] */
__device__ uint16_t wt16[2 * 512 * 512];    /* Wq^T, Wk^T fp16 [z][n][k] */
__device__ uint16_t q16[32 * 512 * 512];    /* q fp16 */
__device__ uint16_t k16[32 * 512 * 512];    /* k fp16 */
__device__ uint16_t at16[32 * 512 * 512];   /* exp(sigmoid(scores)) fp16 */
__device__ uint16_t ax16[32 * 512 * 512];   /* softmax @ x, fp16 */
__device__ float g_rinv[32 * 512];          /* per-row 1/sum(exp) */
__device__ float g_part[KSPLIT * 32 * 512];

/* ------------------------------------------------------------------ */
/* Helpers                                                             */
/* ------------------------------------------------------------------ */
__device__ __forceinline__ uint32_t sptr(const void* p) {
    return (uint32_t)__cvta_generic_to_shared(p);
}

__device__ __forceinline__ void ldsm_x4(uint32_t& r0, uint32_t& r1,
                                        uint32_t& r2, uint32_t& r3,
                                        uint32_t addr) {
    asm volatile("ldmatrix.sync.aligned.m8n8.x4.shared.b16 {%0,%1,%2,%3}, [%4];"
                 : "=r"(r0), "=r"(r1), "=r"(r2), "=r"(r3)
                 : "r"(addr));
}

__device__ __forceinline__ void ldsm_x4_trans(uint32_t& r0, uint32_t& r1,
                                              uint32_t& r2, uint32_t& r3,
                                              uint32_t addr) {
    asm volatile("ldmatrix.sync.aligned.m8n8.x4.trans.shared.b16 {%0,%1,%2,%3}, [%4];"
                 : "=r"(r0), "=r"(r1), "=r"(r2), "=r"(r3)
                 : "r"(addr));
}

__device__ __forceinline__ void mma_f16(float* c, const uint32_t* a,
                                        const uint32_t* b) {
    asm volatile(
        "mma.sync.aligned.m16n8k16.row.col.f32.f16.f16.f32 "
        "{%0,%1,%2,%3}, {%4,%5,%6,%7}, {%8,%9}, {%0,%1,%2,%3};"
        : "+f"(c[0]), "+f"(c[1]), "+f"(c[2]), "+f"(c[3])
        : "r"(a[0]), "r"(a[1]), "r"(a[2]), "r"(a[3]),
          "r"(b[0]), "r"(b[1]));
}

__device__ __forceinline__ void cpa16(uint32_t dst, const void* src) {
    asm volatile("cp.async.cg.shared.global [%0], [%1], 16;"
                 :: "r"(dst), "l"(src) : "memory");
}
__device__ __forceinline__ void cpa_commit() {
    asm volatile("cp.async.commit_group;" ::: "memory");
}
template <int N>
__device__ __forceinline__ void cpa_wait() {
    asm volatile("cp.async.wait_group %0;" :: "n"(N) : "memory");
}

__device__ __forceinline__ uint16_t h1(float v) {
    __half h = __float2half_rn(v);
    return *reinterpret_cast<uint16_t*>(&h);
}

__device__ __forceinline__ void pack8_plain(const float* v, uint4& u) {
    uint16_t h[8];
#pragma unroll
    for (int j = 0; j < 8; j++) {
        h[j] = h1(v[j]);
    }
    u.x = (uint32_t)h[0] | ((uint32_t)h[1] << 16);
    u.y = (uint32_t)h[2] | ((uint32_t)h[3] << 16);
    u.z = (uint32_t)h[4] | ((uint32_t)h[5] << 16);
    u.w = (uint32_t)h[6] | ((uint32_t)h[7] << 16);
}

/* copy one 128x64 fp16 tile (src ld=512, pre-offset by k0) into smem  */
__device__ __forceinline__ void cpa_tile64(uint32_t sdst, const uint16_t* src,
                                           int tid) {
#pragma unroll
    for (int i = 0; i < 4; i++) {
        int q = i * 256 + tid;
        int row = q >> 3;
        int c = (q & 7) * 8;
        cpa16(sdst + (uint32_t)(row * GASTR + c) * 2, src + (size_t)row * 512 + c);
    }
}

/* ------------------------------------------------------------------ */
/* Compute: one GBK=64 slab, 128x128 CTA tile. B fragments for all 4   */
/* k-halves hoisted; 64 MMAs per warp per slab.                        */
/* ------------------------------------------------------------------ */
__device__ __forceinline__ void compute128_h(uint32_t sA, uint32_t sB,
                                             int wm, int wn, int lane,
                                             float acc[4][4][4]) {
    const int lr = (lane & 7) + ((lane >> 3) & 1) * 8;
    const int lc = (lane >> 4) * 8;

    uint32_t b[4][4][2];    /* [ks-half][nt][frag] */
#pragma unroll
    for (int h = 0; h < 4; h++) {
#pragma unroll
        for (int p = 0; p < 2; p++) {
            uint32_t off = (uint32_t)(((wn * 32 + p * 16 + lr) * GASTR + h * 16 + lc) * 2);
            uint32_t r0, r1, r2, r3;
            ldsm_x4(r0, r1, r2, r3, sB + off);
            b[h][2 * p][0] = r0;
            b[h][2 * p][1] = r2;
            b[h][2 * p + 1][0] = r1;
            b[h][2 * p + 1][1] = r3;
        }
    }
#pragma unroll
    for (int h = 0; h < 4; h++) {
        uint32_t a[4][4];
#pragma unroll
        for (int mt = 0; mt < 4; mt++) {
            uint32_t off = (uint32_t)(((wm * 64 + mt * 16 + lr) * GASTR + h * 16 + lc) * 2);
            ldsm_x4(a[mt][0], a[mt][1], a[mt][2], a[mt][3], sA + off);
        }
#pragma unroll
        for (int mt = 0; mt < 4; mt++) {
#pragma unroll
            for (int nt = 0; nt < 4; nt++) {
                mma_f16(acc[mt][nt], a[mt], b[h][nt]);
            }
        }
    }
}

/* ------------------------------------------------------------------ */
/* Prep 1: x -> direct fp16 (xd16) AND transposed fp16 (xt16).         */
/* ------------------------------------------------------------------ */
__global__ __launch_bounds__(256) void prep_x(const float* __restrict__ x) {
    __shared__ float ts[64][65];
    const int tid = threadIdx.x;
    const int m0 = blockIdx.y * 64;
    const int h0 = blockIdx.x * 64;
    const size_t off = (size_t)blockIdx.z * 262144;
    const float* src = x + off + (size_t)m0 * 512 + h0;

#pragma unroll
    for (int i = 0; i < 4; i++) {
        int lin = i * 256 + tid;
        int r = lin >> 4;
        int c4 = (lin & 15) * 4;
        float4 v = *(const float4*)(src + (size_t)r * 512 + c4);
        ts[r][c4 + 0] = v.x;
        ts[r][c4 + 1] = v.y;
        ts[r][c4 + 2] = v.z;
        ts[r][c4 + 3] = v.w;
    }
    __syncthreads();

#pragma unroll
    for (int i = 0; i < 2; i++) {
        int lin = i * 256 + tid;
        int r = lin >> 3;
        int c8 = (lin & 7) * 8;
        float v[8];
#pragma unroll
        for (int j = 0; j < 8; j++) {
            v[j] = ts[r][c8 + j];
        }
        uint4 u;
        pack8_plain(v, u);
        *(uint4*)(xd16 + off + (size_t)(m0 + r) * 512 + h0 + c8) = u;
    }
#pragma unroll
    for (int i = 0; i < 2; i++) {
        int lin = i * 256 + tid;
        int hr = lin >> 3;
        int m8 = (lin & 7) * 8;
        float v[8];
#pragma unroll
        for (int j = 0; j < 8; j++) {
            v[j] = ts[m8 + j][hr];
        }
        uint4 u;
        pack8_plain(v, u);
        *(uint4*)(xt16 + off + (size_t)(h0 + hr) * 512 + m0 + m8) = u;
    }
}

/* ------------------------------------------------------------------ */
/* Prep 2: Wq/Wk -> transposed plain fp16 (wt16). grid (8,8,2).        */
/* ------------------------------------------------------------------ */
__global__ __launch_bounds__(256) void prep_wt(const float* __restrict__ Wq,
                                               const float* __restrict__ Wk) {
    __shared__ float ts[64][65];
    const int tid = threadIdx.x;
    const int k0 = blockIdx.y * 64;
    const int n0 = blockIdx.x * 64;
    const float* src = (blockIdx.z ? Wk : Wq) + (size_t)k0 * 512 + n0;
    const size_t dstoff = (size_t)blockIdx.z * 262144;

#pragma unroll
    for (int i = 0; i < 4; i++) {
        int lin = i * 256 + tid;
        int r = lin >> 4;
        int c4 = (lin & 15) * 4;
        float4 v = *(const float4*)(src + (size_t)r * 512 + c4);
        ts[r][c4 + 0] = v.x;
        ts[r][c4 + 1] = v.y;
        ts[r][c4 + 2] = v.z;
        ts[r][c4 + 3] = v.w;
    }
    __syncthreads();

#pragma unroll
    for (int i = 0; i < 2; i++) {
        int lin = i * 256 + tid;
        int nr = lin >> 3;
        int k8 = (lin & 7) * 8;
        float v[8];
#pragma unroll
        for (int j = 0; j < 8; j++) {
            v[j] = ts[k8 + j][nr];
        }
        uint4 u;
        pack8_plain(v, u);
        *(uint4*)(wt16 + dstoff + (size_t)(n0 + nr) * 512 + k0 + k8) = u;
    }
}

/* ------------------------------------------------------------------ */
/* Generic plain-fp16 GEMM body: 3-stage cp.async pipeline, GBK=64.    */
/* ------------------------------------------------------------------ */
#define PTILE (128 * GASTR)                  /* elems per array */
#define STAGE_BYTES (2 * PTILE * 2)          /* 36864 */
#define GSMEM_BYTES (GSTAGES * STAGE_BYTES)  /* 110592 */

__device__ __forceinline__ void gemm128_body(
    const uint16_t* __restrict__ A, const uint16_t* __restrict__ B,
    uint32_t s0, int tid, int wm, int wn, int lane, float acc[4][4][4]) {
#pragma unroll
    for (int s = 0; s < GSTAGES - 1; s++) {
        uint32_t sb = s0 + s * STAGE_BYTES;
        cpa_tile64(sb, A + s * GBK, tid);
        cpa_tile64(sb + PTILE * 2, B + s * GBK, tid);
        cpa_commit();
    }

    int cur = 0;      /* stage index of slab c, cycles 0,1,2 */
    int nxt = 2;      /* stage index of slab c+2 */
    for (int c = 0; c < GNITER; c++) {
        cpa_wait<1>();
        __syncthreads();
        int nf = c + GSTAGES - 1;
        if (nf < GNITER) {
            uint32_t sb = s0 + nxt * STAGE_BYTES;
            cpa_tile64(sb, A + nf * GBK, tid);
            cpa_tile64(sb + PTILE * 2, B + nf * GBK, tid);
        }
        cpa_commit();   /* unconditional: keeps group count in lockstep */
        uint32_t sb = s0 + cur * STAGE_BYTES;
        compute128_h(sb, sb + PTILE * 2, wm, wn, lane, acc);
        cur = (cur == 2) ? 0 : cur + 1;
        nxt = (nxt == 2) ? 0 : nxt + 1;
    }
}

/* ------------------------------------------------------------------ */
/* Kernel: q/k projections. grid (4, 128, 2), dyn smem, 2 CTAs/SM.     */
/* ------------------------------------------------------------------ */
__global__ __launch_bounds__(256, 2) void proj_kernel(
    const float* __restrict__ bq, const float* __restrict__ bk) {
    extern __shared__ uint16_t dynsm[];

    const int tid = threadIdx.x;
    const int lane = tid & 31;
    const int wid = tid >> 5;
    const int wm = wid & 1;
    const int wn = wid >> 1;
    const int z = blockIdx.z;
    const int row0 = blockIdx.y * 128;
    const int col0 = blockIdx.x * 128;

    const uint16_t* A = xd16 + (size_t)row0 * 512;
    const uint16_t* B = wt16 + (size_t)z * 262144 + (size_t)col0 * 512;

    float acc[4][4][4] = {};
    gemm128_body(A, B, sptr(dynsm), tid, wm, wn, lane, acc);

    const float* bias = z ? bk : bq;
    uint16_t* O = z ? k16 : q16;
    const int g = lane >> 2;
    const int tg2 = (lane & 3) * 2;
#pragma unroll
    for (int mt = 0; mt < 4; mt++) {
        int r = row0 + wm * 64 + mt * 16 + g;
#pragma unroll
        for (int nt = 0; nt < 4; nt++) {
            int c = col0 + wn * 32 + nt * 8 + tg2;
            float2 bv = *(const float2*)(bias + c);
            __half2 p0 = __floats2half2_rn(acc[mt][nt][0] + bv.x, acc[mt][nt][1] + bv.y);
            __half2 p1 = __floats2half2_rn(acc[mt][nt][2] + bv.x, acc[mt][nt][3] + bv.y);
            *(uint32_t*)(O + (size_t)r * 512 + c) = *reinterpret_cast<uint32_t*>(&p0);
            *(uint32_t*)(O + (size_t)(r + 8) * 512 + c) = *reinterpret_cast<uint32_t*>(&p1);
        }
    }
}

/* ------------------------------------------------------------------ */
/* Kernel: scores -> at16 = exp(sigmoid(q k^T / sqrt(512))) fp16.      */
/* ------------------------------------------------------------------ */
__global__ __launch_bounds__(256, 2) void scores_kernel() {
    extern __shared__ uint16_t dynsm[];

    const int tid = threadIdx.x;
    const int lane = tid & 31;
    const int wid = tid >> 5;
    const int wm = wid & 1;
    const int wn = wid >> 1;
    const int b = blockIdx.z;
    const int row0 = blockIdx.y * 128;
    const int col0 = blockIdx.x * 128;

    const uint16_t* A = q16 + ((size_t)b * 512 + row0) * 512;
    const uint16_t* B = k16 + ((size_t)b * 512 + col0) * 512;

    float acc[4][4][4] = {};
    gemm128_body(A, B, sptr(dynsm), tid, wm, wn, lane, acc);

    const float scale = 0.04419417382415922f; /* 1/sqrt(512) */
    uint16_t* E = at16 + (size_t)b * 262144;
    const int g = lane >> 2;
    const int tg2 = (lane & 3) * 2;
#pragma unroll
    for (int mt = 0; mt < 4; mt++) {
        int r = row0 + wm * 64 + mt * 16 + g;
#pragma unroll
        for (int nt = 0; nt < 4; nt++) {
            int c = col0 + wn * 32 + nt * 8 + tg2;
            float e0 = expf(1.f / (1.f + expf(-acc[mt][nt][0] * scale)));
            float e1 = expf(1.f / (1.f + expf(-acc[mt][nt][1] * scale)));
            float e2 = expf(1.f / (1.f + expf(-acc[mt][nt][2] * scale)));
            float e3 = expf(1.f / (1.f + expf(-acc[mt][nt][3] * scale)));
            __half2 p0 = __floats2half2_rn(e0, e1);
            __half2 p1 = __floats2half2_rn(e2, e3);
            *(uint32_t*)(E + (size_t)r * 512 + c) = *reinterpret_cast<uint32_t*>(&p0);
            *(uint32_t*)(E + (size_t)(r + 8) * 512 + c) = *reinterpret_cast<uint32_t*>(&p1);
        }
    }
}

/* ------------------------------------------------------------------ */
/* Kernel: warp-per-row rowsum. Reads at16, writes normalized fp32     */
/* attn and g_rinv. grid 2048 x 256.                                   */
/* ------------------------------------------------------------------ */
__global__ __launch_bounds__(256) void rowsum_kernel(float* __restrict__ attn) {
    const int w = threadIdx.x >> 5;
    const int lane = threadIdx.x & 31;
    const size_t row = (size_t)blockIdx.x * 8 + w;
    const size_t base = row * 512;

    uint2 u[4];
#pragma unroll
    for (int i = 0; i < 4; i++) {
        u[i] = *(const uint2*)(at16 + base + i * 128 + lane * 4);
    }
    float e[16];
    float s = 0.f;
#pragma unroll
    for (int i = 0; i < 4; i++) {
        __half2 h0 = *reinterpret_cast<__half2*>(&u[i].x);
        __half2 h1v = *reinterpret_cast<__half2*>(&u[i].y);
        float2 f0 = __half22float2(h0);
        float2 f1 = __half22float2(h1v);
        e[i * 4 + 0] = f0.x;
        e[i * 4 + 1] = f0.y;
        e[i * 4 + 2] = f1.x;
        e[i * 4 + 3] = f1.y;
        s += f0.x + f0.y + f1.x + f1.y;
    }
#pragma unroll
    for (int o = 16; o > 0; o >>= 1) {
        s += __shfl_xor_sync(0xffffffffu, s, o);
    }
    const float inv = 1.f / s;
    if (lane == 0) {
        g_rinv[row] = inv;
    }
#pragma unroll
    for (int i = 0; i < 4; i++) {
        float4 o;
        o.x = e[i * 4 + 0] * inv;
        o.y = e[i * 4 + 1] * inv;
        o.z = e[i * 4 + 2] * inv;
        o.w = e[i * 4 + 3] * inv;
        *(float4*)(attn + base + i * 128 + lane * 4) = o;
    }
}

/* ------------------------------------------------------------------ */
/* Kernel: ax = softmax @ x via exp-A GEMM + per-row 1/sum epilogue.   */
/* ------------------------------------------------------------------ */
__global__ __launch_bounds__(256, 2) void ax_kernel() {
    extern __shared__ uint16_t dynsm[];

    const int tid = threadIdx.x;
    const int lane = tid & 31;
    const int wid = tid >> 5;
    const int wm = wid & 1;
    const int wn = wid >> 1;
    const int b = blockIdx.z;
    const int row0 = blockIdx.y * 128;
    const int col0 = blockIdx.x * 128;

    const uint16_t* A = at16 + ((size_t)b * 512 + row0) * 512;
    const uint16_t* B = xt16 + ((size_t)b * 512 + col0) * 512;

    float acc[4][4][4] = {};
    gemm128_body(A, B, sptr(dynsm), tid, wm, wn, lane, acc);

    const size_t rowg = (size_t)b * 512;
    const int g = lane >> 2;
    const int tg2 = (lane & 3) * 2;
#pragma unroll
    for (int mt = 0; mt < 4; mt++) {
        int r = row0 + wm * 64 + mt * 16 + g;
        float i0 = g_rinv[rowg + r];
        float i1 = g_rinv[rowg + r + 8];
#pragma unroll
        for (int nt = 0; nt < 4; nt++) {
            int c = col0 + wn * 32 + nt * 8 + tg2;
            __half2 p0 = __floats2half2_rn(acc[mt][nt][0] * i0, acc[mt][nt][1] * i0);
            __half2 p1 = __floats2half2_rn(acc[mt][nt][2] * i1, acc[mt][nt][3] * i1);
            *(uint32_t*)(ax16 + (rowg + r) * 512 + c) = *reinterpret_cast<uint32_t*>(&p0);
            *(uint32_t*)(ax16 + (rowg + r + 8) * 512 + c) = *reinterpret_cast<uint32_t*>(&p1);
        }
    }
}

/* ------------------------------------------------------------------ */
/* Kernel: split-K partials of out = ax.reshape(32,262144) @ Wm.       */
/* B in native [k][n] smem layout, ldmatrix.trans fetch. grid (4,64).  */
/* (unchanged — measured at the LTS bandwidth cap)                     */
/* ------------------------------------------------------------------ */
#define FAEL (32 * FASTR)              /* A stage elems: [m][k] */
#define FBEL (32 * BN_LD)              /* B stage elems: [k][n] */
#define FSTAGE (FAEL + FBEL)

__global__ __launch_bounds__(256, 2) void final_kernel(const float* __restrict__ Wm) {
    __shared__ alignas(16) uint16_t dsm[2 * FSTAGE];

    const int tid = threadIdx.x;
    const int lane = tid & 31;
    const int wid = tid >> 5;
    const int col0 = blockIdx.x * 128;
    const size_t kbase = (size_t)blockIdx.y * KCHUNK;

    float acc[2][2][4] = {};
    uint2 va;
    float4 vb[4];
    const int am = tid >> 3;
    const int ak = (tid & 7) * 4;
    const int bk_r = tid >> 5;
    const int bn4 = (tid & 31) * 4;

    va = *(const uint2*)(ax16 + (size_t)am * 262144 + kbase + ak);
#pragma unroll
    for (int i = 0; i < 4; i++) {
        vb[i] = *(const float4*)(Wm + (kbase + bk_r + i * 8) * 512 + col0 + bn4);
    }

    auto store_stage = [&](uint16_t* stg) {
        *(uint2*)(stg + am * FASTR + ak) = va;
        uint16_t* bs = stg + FAEL;
#pragma unroll
        for (int i = 0; i < 4; i++) {
            __half2 p0 = __floats2half2_rn(vb[i].x, vb[i].y);
            __half2 p1 = __floats2half2_rn(vb[i].z, vb[i].w);
            uint2 u;
            u.x = *reinterpret_cast<uint32_t*>(&p0);
            u.y = *reinterpret_cast<uint32_t*>(&p1);
            *(uint2*)(bs + (bk_r + i * 8) * BN_LD + bn4) = u;
        }
    };

    store_stage(dsm);
    va = *(const uint2*)(ax16 + (size_t)am * 262144 + kbase + FBK + ak);
#pragma unroll
    for (int i = 0; i < 4; i++) {
        vb[i] = *(const float4*)(Wm + (kbase + FBK + bk_r + i * 8) * 512 + col0 + bn4);
    }
    __syncthreads();

    const int lr = (lane & 7) + ((lane >> 3) & 1) * 8;
    const int lc = (lane >> 4) * 8;
    const int trow = (lane >> 4) * 8 + (lane & 7);
    const int tcol = ((lane >> 3) & 1) * 8;

    for (int k0 = 0; k0 < KCHUNK; k0 += FBK) {
        int cur = (k0 >> 5) & 1;
        if (k0 + FBK < KCHUNK) {
            store_stage(dsm + (cur ^ 1) * FSTAGE);
        }
        if (k0 + 2 * FBK < KCHUNK) {
            va = *(const uint2*)(ax16 + (size_t)am * 262144 + kbase + k0 + 2 * FBK + ak);
#pragma unroll
            for (int i = 0; i < 4; i++) {
                vb[i] = *(const float4*)(Wm + (kbase + k0 + 2 * FBK + bk_r + i * 8) * 512 +
                                         col0 + bn4);
            }
        }
        uint32_t base = sptr(dsm) + cur * FSTAGE * 2;
        uint32_t sA = base;
        uint32_t sB = base + FAEL * 2;
#pragma unroll
        for (int ks = 0; ks < FBK; ks += 16) {
            uint32_t bf[2][2];
            uint32_t offb = (uint32_t)(((ks + trow) * BN_LD + wid * 16 + tcol) * 2);
            uint32_t r0, r1, r2, r3;
            ldsm_x4_trans(r0, r1, r2, r3, sB + offb);
            bf[0][0] = r0;
            bf[1][0] = r1;
            bf[0][1] = r2;
            bf[1][1] = r3;
            uint32_t a[2][4];
#pragma unroll
            for (int mt = 0; mt < 2; mt++) {
                uint32_t offa = (uint32_t)(((mt * 16 + lr) * FASTR + ks + lc) * 2);
                ldsm_x4(a[mt][0], a[mt][1], a[mt][2], a[mt][3], sA + offa);
            }
#pragma unroll
            for (int mt = 0; mt < 2; mt++) {
#pragma unroll
                for (int nt = 0; nt < 2; nt++) {
                    mma_f16(acc[mt][nt], a[mt], bf[nt]);
                }
            }
        }
        __syncthreads();
    }

    const int g = lane >> 2;
    const int tg2 = (lane & 3) * 2;
    float* P = g_part + (size_t)blockIdx.y * 16384;
#pragma unroll
    for (int mt = 0; mt < 2; mt++) {
        int r = mt * 16 + g;
#pragma unroll
        for (int nt = 0; nt < 2; nt++) {
            int c = col0 + wid * 16 + nt * 8 + tg2;
            float2 o0;
            float2 o1;
            o0.x = acc[mt][nt][0];
            o0.y = acc[mt][nt][1];
            o1.x = acc[mt][nt][2];
            o1.y = acc[mt][nt][3];
            *(float2*)(P + (size_t)r * 512 + c) = o0;
            *(float2*)(P + (size_t)(r + 8) * 512 + c) = o1;
        }
    }
}

/* ------------------------------------------------------------------ */
/* Kernel: deterministic split-K reduce + bias. grid 64 x 256.         */
/* ------------------------------------------------------------------ */
__global__ __launch_bounds__(256) void reduce_kernel(float* __restrict__ out,
                                                     const float* __restrict__ bm) {
    const int idx = blockIdx.x * 256 + threadIdx.x;
    const int n = idx & 511;
    float sum = bm[n];
#pragma unroll 8
    for (int s = 0; s < KSPLIT; s++) {
        sum += g_part[(size_t)s * 16384 + idx];
    }
    out[idx] = sum;
}

/* ------------------------------------------------------------------ */
extern "C" void kernel_launch(void* const* d_in, const int* in_sizes, int n_in,
                              void* d_out, int out_size) {
    const float* x = (const float*)d_in[0];
    const float* Wq = (const float*)d_in[1];
    const float* bq = (const float*)d_in[2];
    const float* Wk = (const float*)d_in[3];
    const float* bk = (const float*)d_in[4];
    const float* Wm = (const float*)d_in[5];
    const float* bm = (const float*)d_in[6];

    float* out = (float*)d_out;   /* [32, 512] */
    float* attn = out + 32 * 512; /* [32, 512, 512] */

    cudaFuncSetAttribute(proj_kernel, cudaFuncAttributeMaxDynamicSharedMemorySize,
                         GSMEM_BYTES);
    cudaFuncSetAttribute(scores_kernel, cudaFuncAttributeMaxDynamicSharedMemorySize,
                         GSMEM_BYTES);
    cudaFuncSetAttribute(ax_kernel, cudaFuncAttributeMaxDynamicSharedMemorySize,
                         GSMEM_BYTES);

    prep_x<<<dim3(8, 8, 32), 256>>>(x);
    prep_wt<<<dim3(8, 8, 2), 256>>>(Wq, Wk);
    proj_kernel<<<dim3(4, 128, 2), 256, GSMEM_BYTES>>>(bq, bk);
    scores_kernel<<<dim3(4, 4, 32), 256, GSMEM_BYTES>>>();
    rowsum_kernel<<<2048, 256>>>(attn);
    ax_kernel<<<dim3(4, 4, 32), 256, GSMEM_BYTES>>>();
    final_kernel<<<dim3(4, KSPLIT), 256>>>(Wm);
    reduce_kernel<<<64, 256>>>(out, bm);
}

// round 12
// speedup vs baseline: 1.0734x; 1.0224x over previous
#include <cuda_runtime.h>
#include <cuda_fp16.h>
#include <stdint.h>
#include <math.h>

/* GEMM-trio pipeline constants */
#define GBK 64             /* k per slab */
#define GASTR 72           /* padded smem stride (144 B rows, 16B aligned) */
#define GNITER 8           /* K=512 / GBK */
#define GSTAGES 3

/* final kernel constants */
#define FBK 32
#define FASTR 40
#define KSPLIT 64
#define KCHUNK 4096
#define BN_LD 136

/* Scratch: __device__ globals (allocation-free rule) */
__device__ uint16_t xd16[32 * 512 * 512];   /* x direct fp16 [b*512+n][h] */
__device__ uint16_t xt16[32 * 512 * 512];   /* x^T fp16 [b][h][m] */
__device__ uint16_t wt16[2 * 512 * 512];    /* Wq^T, Wk^T fp16 [z][n][k] */
__device__ uint16_t q16[32 * 512 * 512];    /* q fp16 */
__device__ uint16_t k16[32 * 512 * 512];    /* k fp16 */
__device__ uint16_t at16[32 * 512 * 512];   /* exp(sigmoid(scores)) fp16 */
__device__ uint16_t ax16[32 * 512 * 512];   /* softmax @ x, fp16 */
__device__ float g_rinv[32 * 512];          /* per-row 1/sum(exp) */
__device__ float g_part[KSPLIT * 32 * 512];

/* ------------------------------------------------------------------ */
/* Helpers                                                             */
/* ------------------------------------------------------------------ */
__device__ __forceinline__ uint32_t sptr(const void* p) {
    return (uint32_t)__cvta_generic_to_shared(p);
}

__device__ __forceinline__ void ldsm_x4(uint32_t& r0, uint32_t& r1,
                                        uint32_t& r2, uint32_t& r3,
                                        uint32_t addr) {
    asm volatile("ldmatrix.sync.aligned.m8n8.x4.shared.b16 {%0,%1,%2,%3}, [%4];"
                 : "=r"(r0), "=r"(r1), "=r"(r2), "=r"(r3)
                 : "r"(addr));
}

__device__ __forceinline__ void ldsm_x4_trans(uint32_t& r0, uint32_t& r1,
                                              uint32_t& r2, uint32_t& r3,
                                              uint32_t addr) {
    asm volatile("ldmatrix.sync.aligned.m8n8.x4.trans.shared.b16 {%0,%1,%2,%3}, [%4];"
                 : "=r"(r0), "=r"(r1), "=r"(r2), "=r"(r3)
                 : "r"(addr));
}

__device__ __forceinline__ void mma_f16(float* c, const uint32_t* a,
                                        const uint32_t* b) {
    asm volatile(
        "mma.sync.aligned.m16n8k16.row.col.f32.f16.f16.f32 "
        "{%0,%1,%2,%3}, {%4,%5,%6,%7}, {%8,%9}, {%0,%1,%2,%3};"
        : "+f"(c[0]), "+f"(c[1]), "+f"(c[2]), "+f"(c[3])
        : "r"(a[0]), "r"(a[1]), "r"(a[2]), "r"(a[3]),
          "r"(b[0]), "r"(b[1]));
}

__device__ __forceinline__ void cpa16(uint32_t dst, const void* src) {
    asm volatile("cp.async.cg.shared.global [%0], [%1], 16;"
                 :: "r"(dst), "l"(src) : "memory");
}
__device__ __forceinline__ void cpa_commit() {
    asm volatile("cp.async.commit_group;" ::: "memory");
}
template <int N>
__device__ __forceinline__ void cpa_wait() {
    asm volatile("cp.async.wait_group %0;" :: "n"(N) : "memory");
}

__device__ __forceinline__ uint16_t h1(float v) {
    __half h = __float2half_rn(v);
    return *reinterpret_cast<uint16_t*>(&h);
}

__device__ __forceinline__ void pack8_plain(const float* v, uint4& u) {
    uint16_t h[8];
#pragma unroll
    for (int j = 0; j < 8; j++) {
        h[j] = h1(v[j]);
    }
    u.x = (uint32_t)h[0] | ((uint32_t)h[1] << 16);
    u.y = (uint32_t)h[2] | ((uint32_t)h[3] << 16);
    u.z = (uint32_t)h[4] | ((uint32_t)h[5] << 16);
    u.w = (uint32_t)h[6] | ((uint32_t)h[7] << 16);
}

/* ------------------------------------------------------------------ */
/* Compute: one GBK=64 slab, 128x128 CTA tile. B fragments for all 4   */
/* k-halves hoisted; 64 MMAs per warp per slab.                        */
/* ------------------------------------------------------------------ */
__device__ __forceinline__ void compute128_h(uint32_t sA, uint32_t sB,
                                             int wm, int wn, int lane,
                                             float acc[4][4][4]) {
    const int lr = (lane & 7) + ((lane >> 3) & 1) * 8;
    const int lc = (lane >> 4) * 8;

    uint32_t b[4][4][2];    /* [ks-half][nt][frag] */
#pragma unroll
    for (int h = 0; h < 4; h++) {
#pragma unroll
        for (int p = 0; p < 2; p++) {
            uint32_t off = (uint32_t)(((wn * 32 + p * 16 + lr) * GASTR + h * 16 + lc) * 2);
            uint32_t r0, r1, r2, r3;
            ldsm_x4(r0, r1, r2, r3, sB + off);
            b[h][2 * p][0] = r0;
            b[h][2 * p][1] = r2;
            b[h][2 * p + 1][0] = r1;
            b[h][2 * p + 1][1] = r3;
        }
    }
#pragma unroll
    for (int h = 0; h < 4; h++) {
        uint32_t a[4][4];
#pragma unroll
        for (int mt = 0; mt < 4; mt++) {
            uint32_t off = (uint32_t)(((wm * 64 + mt * 16 + lr) * GASTR + h * 16 + lc) * 2);
            ldsm_x4(a[mt][0], a[mt][1], a[mt][2], a[mt][3], sA + off);
        }
#pragma unroll
        for (int mt = 0; mt < 4; mt++) {
#pragma unroll
            for (int nt = 0; nt < 4; nt++) {
                mma_f16(acc[mt][nt], a[mt], b[h][nt]);
            }
        }
    }
}

/* ------------------------------------------------------------------ */
/* Prep 1: x -> direct fp16 (xd16) AND transposed fp16 (xt16).         */
/* ------------------------------------------------------------------ */
__global__ __launch_bounds__(256) void prep_x(const float* __restrict__ x) {
    __shared__ float ts[64][65];
    const int tid = threadIdx.x;
    const int m0 = blockIdx.y * 64;
    const int h0 = blockIdx.x * 64;
    const size_t off = (size_t)blockIdx.z * 262144;
    const float* src = x + off + (size_t)m0 * 512 + h0;

#pragma unroll
    for (int i = 0; i < 4; i++) {
        int lin = i * 256 + tid;
        int r = lin >> 4;
        int c4 = (lin & 15) * 4;
        float4 v = *(const float4*)(src + (size_t)r * 512 + c4);
        ts[r][c4 + 0] = v.x;
        ts[r][c4 + 1] = v.y;
        ts[r][c4 + 2] = v.z;
        ts[r][c4 + 3] = v.w;
    }
    __syncthreads();

#pragma unroll
    for (int i = 0; i < 2; i++) {
        int lin = i * 256 + tid;
        int r = lin >> 3;
        int c8 = (lin & 7) * 8;
        float v[8];
#pragma unroll
        for (int j = 0; j < 8; j++) {
            v[j] = ts[r][c8 + j];
        }
        uint4 u;
        pack8_plain(v, u);
        *(uint4*)(xd16 + off + (size_t)(m0 + r) * 512 + h0 + c8) = u;
    }
#pragma unroll
    for (int i = 0; i < 2; i++) {
        int lin = i * 256 + tid;
        int hr = lin >> 3;
        int m8 = (lin & 7) * 8;
        float v[8];
#pragma unroll
        for (int j = 0; j < 8; j++) {
            v[j] = ts[m8 + j][hr];
        }
        uint4 u;
        pack8_plain(v, u);
        *(uint4*)(xt16 + off + (size_t)(h0 + hr) * 512 + m0 + m8) = u;
    }
}

/* ------------------------------------------------------------------ */
/* Prep 2: Wq/Wk -> transposed plain fp16 (wt16). grid (8,8,2).        */
/* ------------------------------------------------------------------ */
__global__ __launch_bounds__(256) void prep_wt(const float* __restrict__ Wq,
                                               const float* __restrict__ Wk) {
    __shared__ float ts[64][65];
    const int tid = threadIdx.x;
    const int k0 = blockIdx.y * 64;
    const int n0 = blockIdx.x * 64;
    const float* src = (blockIdx.z ? Wk : Wq) + (size_t)k0 * 512 + n0;
    const size_t dstoff = (size_t)blockIdx.z * 262144;

#pragma unroll
    for (int i = 0; i < 4; i++) {
        int lin = i * 256 + tid;
        int r = lin >> 4;
        int c4 = (lin & 15) * 4;
        float4 v = *(const float4*)(src + (size_t)r * 512 + c4);
        ts[r][c4 + 0] = v.x;
        ts[r][c4 + 1] = v.y;
        ts[r][c4 + 2] = v.z;
        ts[r][c4 + 3] = v.w;
    }
    __syncthreads();

#pragma unroll
    for (int i = 0; i < 2; i++) {
        int lin = i * 256 + tid;
        int nr = lin >> 3;
        int k8 = (lin & 7) * 8;
        float v[8];
#pragma unroll
        for (int j = 0; j < 8; j++) {
            v[j] = ts[k8 + j][nr];
        }
        uint4 u;
        pack8_plain(v, u);
        *(uint4*)(wt16 + dstoff + (size_t)(n0 + nr) * 512 + k0 + k8) = u;
    }
}

/* ------------------------------------------------------------------ */
/* Generic plain-fp16 GEMM body: 3-stage cp.async pipeline, GBK=64.    */
/* Pointer-increment addressing: per-thread gmem ptrs advance by GBK,  */
/* smem dst offsets are (stage const + fixed thread offset).           */
/* ------------------------------------------------------------------ */
#define PTILE (128 * GASTR)                  /* elems per array */
#define STAGE_BYTES (2 * PTILE * 2)          /* 36864 */
#define GSMEM_BYTES (GSTAGES * STAGE_BYTES)  /* 110592 */

__device__ __forceinline__ void gemm128_body(
    const uint16_t* __restrict__ A, const uint16_t* __restrict__ B,
    uint32_t s0, int tid, int wm, int wn, int lane, float acc[4][4][4]) {
    /* fixed per-thread load geometry: rows tid>>3 + 32*i, col (tid&7)*8 */
    const int trow = tid >> 3;
    const int tcol = (tid & 7) * 8;
    const uint16_t* pa = A + (size_t)trow * 512 + tcol;
    const uint16_t* pb = B + (size_t)trow * 512 + tcol;
    const uint32_t soff = (uint32_t)(trow * GASTR + tcol) * 2;

#pragma unroll
    for (int s = 0; s < GSTAGES - 1; s++) {
        uint32_t sb = s0 + s * STAGE_BYTES + soff;
#pragma unroll
        for (int i = 0; i < 4; i++) {
            cpa16(sb + i * (32 * GASTR * 2), pa + i * (32 * 512));
            cpa16(sb + PTILE * 2 + i * (32 * GASTR * 2), pb + i * (32 * 512));
        }
        cpa_commit();
        pa += GBK;
        pb += GBK;
    }

    int cur = 0;      /* stage index of slab c */
    int nxt = 2;      /* stage index of slab c+2 */
    for (int c = 0; c < GNITER; c++) {
        cpa_wait<1>();
        __syncthreads();
        if (c + GSTAGES - 1 < GNITER) {
            uint32_t sb = s0 + nxt * STAGE_BYTES + soff;
#pragma unroll
            for (int i = 0; i < 4; i++) {
                cpa16(sb + i * (32 * GASTR * 2), pa + i * (32 * 512));
                cpa16(sb + PTILE * 2 + i * (32 * GASTR * 2), pb + i * (32 * 512));
            }
            pa += GBK;
            pb += GBK;
        }
        cpa_commit();   /* unconditional: keeps group count in lockstep */
        uint32_t sb = s0 + cur * STAGE_BYTES;
        compute128_h(sb, sb + PTILE * 2, wm, wn, lane, acc);
        cur = (cur == 2) ? 0 : cur + 1;
        nxt = (nxt == 2) ? 0 : nxt + 1;
    }
}

/* ------------------------------------------------------------------ */
/* Kernel: q/k projections. grid (4, 128, 2), dyn smem, 2 CTAs/SM.     */
/* ------------------------------------------------------------------ */
__global__ __launch_bounds__(256, 2) void proj_kernel(
    const float* __restrict__ bq, const float* __restrict__ bk) {
    extern __shared__ uint16_t dynsm[];

    const int tid = threadIdx.x;
    const int lane = tid & 31;
    const int wid = tid >> 5;
    const int wm = wid & 1;
    const int wn = wid >> 1;
    const int z = blockIdx.z;
    const int row0 = blockIdx.y * 128;
    const int col0 = blockIdx.x * 128;

    const uint16_t* A = xd16 + (size_t)row0 * 512;
    const uint16_t* B = wt16 + (size_t)z * 262144 + (size_t)col0 * 512;

    float acc[4][4][4] = {};
    gemm128_body(A, B, sptr(dynsm), tid, wm, wn, lane, acc);

    const float* bias = z ? bk : bq;
    uint16_t* O = z ? k16 : q16;
    const int g = lane >> 2;
    const int tg2 = (lane & 3) * 2;
#pragma unroll
    for (int mt = 0; mt < 4; mt++) {
        int r = row0 + wm * 64 + mt * 16 + g;
#pragma unroll
        for (int nt = 0; nt < 4; nt++) {
            int c = col0 + wn * 32 + nt * 8 + tg2;
            float2 bv = *(const float2*)(bias + c);
            __half2 p0 = __floats2half2_rn(acc[mt][nt][0] + bv.x, acc[mt][nt][1] + bv.y);
            __half2 p1 = __floats2half2_rn(acc[mt][nt][2] + bv.x, acc[mt][nt][3] + bv.y);
            *(uint32_t*)(O + (size_t)r * 512 + c) = *reinterpret_cast<uint32_t*>(&p0);
            *(uint32_t*)(O + (size_t)(r + 8) * 512 + c) = *reinterpret_cast<uint32_t*>(&p1);
        }
    }
}

/* ------------------------------------------------------------------ */
/* Kernel: scores -> at16 = exp(sigmoid(q k^T / sqrt(512))) fp16.      */
/* Fast-math epilogue (MUFU.EX2 / fast div).                           */
/* ------------------------------------------------------------------ */
__device__ __forceinline__ float esig(float x, float scale) {
    return __expf(__fdividef(1.f, 1.f + __expf(-x * scale)));
}

__global__ __launch_bounds__(256, 2) void scores_kernel() {
    extern __shared__ uint16_t dynsm[];

    const int tid = threadIdx.x;
    const int lane = tid & 31;
    const int wid = tid >> 5;
    const int wm = wid & 1;
    const int wn = wid >> 1;
    const int b = blockIdx.z;
    const int row0 = blockIdx.y * 128;
    const int col0 = blockIdx.x * 128;

    const uint16_t* A = q16 + ((size_t)b * 512 + row0) * 512;
    const uint16_t* B = k16 + ((size_t)b * 512 + col0) * 512;

    float acc[4][4][4] = {};
    gemm128_body(A, B, sptr(dynsm), tid, wm, wn, lane, acc);

    const float scale = 0.04419417382415922f; /* 1/sqrt(512) */
    uint16_t* E = at16 + (size_t)b * 262144;
    const int g = lane >> 2;
    const int tg2 = (lane & 3) * 2;
#pragma unroll
    for (int mt = 0; mt < 4; mt++) {
        int r = row0 + wm * 64 + mt * 16 + g;
#pragma unroll
        for (int nt = 0; nt < 4; nt++) {
            int c = col0 + wn * 32 + nt * 8 + tg2;
            __half2 p0 = __floats2half2_rn(esig(acc[mt][nt][0], scale),
                                           esig(acc[mt][nt][1], scale));
            __half2 p1 = __floats2half2_rn(esig(acc[mt][nt][2], scale),
                                           esig(acc[mt][nt][3], scale));
            *(uint32_t*)(E + (size_t)r * 512 + c) = *reinterpret_cast<uint32_t*>(&p0);
            *(uint32_t*)(E + (size_t)(r + 8) * 512 + c) = *reinterpret_cast<uint32_t*>(&p1);
        }
    }
}

/* ------------------------------------------------------------------ */
/* Kernel: warp-per-row rowsum. Reads at16, writes normalized fp32     */
/* attn and g_rinv. grid 2048 x 256.                                   */
/* ------------------------------------------------------------------ */
__global__ __launch_bounds__(256) void rowsum_kernel(float* __restrict__ attn) {
    const int w = threadIdx.x >> 5;
    const int lane = threadIdx.x & 31;
    const size_t row = (size_t)blockIdx.x * 8 + w;
    const size_t base = row * 512;

    uint2 u[4];
#pragma unroll
    for (int i = 0; i < 4; i++) {
        u[i] = *(const uint2*)(at16 + base + i * 128 + lane * 4);
    }
    float e[16];
    float s = 0.f;
#pragma unroll
    for (int i = 0; i < 4; i++) {
        __half2 h0 = *reinterpret_cast<__half2*>(&u[i].x);
        __half2 h1v = *reinterpret_cast<__half2*>(&u[i].y);
        float2 f0 = __half22float2(h0);
        float2 f1 = __half22float2(h1v);
        e[i * 4 + 0] = f0.x;
        e[i * 4 + 1] = f0.y;
        e[i * 4 + 2] = f1.x;
        e[i * 4 + 3] = f1.y;
        s += f0.x + f0.y + f1.x + f1.y;
    }
#pragma unroll
    for (int o = 16; o > 0; o >>= 1) {
        s += __shfl_xor_sync(0xffffffffu, s, o);
    }
    const float inv = 1.f / s;
    if (lane == 0) {
        g_rinv[row] = inv;
    }
#pragma unroll
    for (int i = 0; i < 4; i++) {
        float4 o;
        o.x = e[i * 4 + 0] * inv;
        o.y = e[i * 4 + 1] * inv;
        o.z = e[i * 4 + 2] * inv;
        o.w = e[i * 4 + 3] * inv;
        *(float4*)(attn + base + i * 128 + lane * 4) = o;
    }
}

/* ------------------------------------------------------------------ */
/* Kernel: ax = softmax @ x via exp-A GEMM + per-row 1/sum epilogue.   */
/* ------------------------------------------------------------------ */
__global__ __launch_bounds__(256, 2) void ax_kernel() {
    extern __shared__ uint16_t dynsm[];

    const int tid = threadIdx.x;
    const int lane = tid & 31;
    const int wid = tid >> 5;
    const int wm = wid & 1;
    const int wn = wid >> 1;
    const int b = blockIdx.z;
    const int row0 = blockIdx.y * 128;
    const int col0 = blockIdx.x * 128;

    const uint16_t* A = at16 + ((size_t)b * 512 + row0) * 512;
    const uint16_t* B = xt16 + ((size_t)b * 512 + col0) * 512;

    float acc[4][4][4] = {};
    gemm128_body(A, B, sptr(dynsm), tid, wm, wn, lane, acc);

    const size_t rowg = (size_t)b * 512;
    const int g = lane >> 2;
    const int tg2 = (lane & 3) * 2;
#pragma unroll
    for (int mt = 0; mt < 4; mt++) {
        int r = row0 + wm * 64 + mt * 16 + g;
        float i0 = g_rinv[rowg + r];
        float i1 = g_rinv[rowg + r + 8];
#pragma unroll
        for (int nt = 0; nt < 4; nt++) {
            int c = col0 + wn * 32 + nt * 8 + tg2;
            __half2 p0 = __floats2half2_rn(acc[mt][nt][0] * i0, acc[mt][nt][1] * i0);
            __half2 p1 = __floats2half2_rn(acc[mt][nt][2] * i1, acc[mt][nt][3] * i1);
            *(uint32_t*)(ax16 + (rowg + r) * 512 + c) = *reinterpret_cast<uint32_t*>(&p0);
            *(uint32_t*)(ax16 + (rowg + r + 8) * 512 + c) = *reinterpret_cast<uint32_t*>(&p1);
        }
    }
}

/* ------------------------------------------------------------------ */
/* Kernel: split-K partials of out = ax.reshape(32,262144) @ Wm.       */
/* (unchanged — measured at the LTS bandwidth cap)                     */
/* ------------------------------------------------------------------ */
#define FAEL (32 * FASTR)              /* A stage elems: [m][k] */
#define FBEL (32 * BN_LD)              /* B stage elems: [k][n] */
#define FSTAGE (FAEL + FBEL)

__global__ __launch_bounds__(256, 2) void final_kernel(const float* __restrict__ Wm) {
    __shared__ alignas(16) uint16_t dsm[2 * FSTAGE];

    const int tid = threadIdx.x;
    const int lane = tid & 31;
    const int wid = tid >> 5;
    const int col0 = blockIdx.x * 128;
    const size_t kbase = (size_t)blockIdx.y * KCHUNK;

    float acc[2][2][4] = {};
    uint2 va;
    float4 vb[4];
    const int am = tid >> 3;
    const int ak = (tid & 7) * 4;
    const int bk_r = tid >> 5;
    const int bn4 = (tid & 31) * 4;

    va = *(const uint2*)(ax16 + (size_t)am * 262144 + kbase + ak);
#pragma unroll
    for (int i = 0; i < 4; i++) {
        vb[i] = *(const float4*)(Wm + (kbase + bk_r + i * 8) * 512 + col0 + bn4);
    }

    auto store_stage = [&](uint16_t* stg) {
        *(uint2*)(stg + am * FASTR + ak) = va;
        uint16_t* bs = stg + FAEL;
#pragma unroll
        for (int i = 0; i < 4; i++) {
            __half2 p0 = __floats2half2_rn(vb[i].x, vb[i].y);
            __half2 p1 = __floats2half2_rn(vb[i].z, vb[i].w);
            uint2 u;
            u.x = *reinterpret_cast<uint32_t*>(&p0);
            u.y = *reinterpret_cast<uint32_t*>(&p1);
            *(uint2*)(bs + (bk_r + i * 8) * BN_LD + bn4) = u;
        }
    };

    store_stage(dsm);
    va = *(const uint2*)(ax16 + (size_t)am * 262144 + kbase + FBK + ak);
#pragma unroll
    for (int i = 0; i < 4; i++) {
        vb[i] = *(const float4*)(Wm + (kbase + FBK + bk_r + i * 8) * 512 + col0 + bn4);
    }
    __syncthreads();

    const int lr = (lane & 7) + ((lane >> 3) & 1) * 8;
    const int lc = (lane >> 4) * 8;
    const int trow = (lane >> 4) * 8 + (lane & 7);
    const int tcol = ((lane >> 3) & 1) * 8;

    for (int k0 = 0; k0 < KCHUNK; k0 += FBK) {
        int cur = (k0 >> 5) & 1;
        if (k0 + FBK < KCHUNK) {
            store_stage(dsm + (cur ^ 1) * FSTAGE);
        }
        if (k0 + 2 * FBK < KCHUNK) {
            va = *(const uint2*)(ax16 + (size_t)am * 262144 + kbase + k0 + 2 * FBK + ak);
#pragma unroll
            for (int i = 0; i < 4; i++) {
                vb[i] = *(const float4*)(Wm + (kbase + k0 + 2 * FBK + bk_r + i * 8) * 512 +
                                         col0 + bn4);
            }
        }
        uint32_t base = sptr(dsm) + cur * FSTAGE * 2;
        uint32_t sA = base;
        uint32_t sB = base + FAEL * 2;
#pragma unroll
        for (int ks = 0; ks < FBK; ks += 16) {
            uint32_t bf[2][2];
            uint32_t offb = (uint32_t)(((ks + trow) * BN_LD + wid * 16 + tcol) * 2);
            uint32_t r0, r1, r2, r3;
            ldsm_x4_trans(r0, r1, r2, r3, sB + offb);
            bf[0][0] = r0;
            bf[1][0] = r1;
            bf[0][1] = r2;
            bf[1][1] = r3;
            uint32_t a[2][4];
#pragma unroll
            for (int mt = 0; mt < 2; mt++) {
                uint32_t offa = (uint32_t)(((mt * 16 + lr) * FASTR + ks + lc) * 2);
                ldsm_x4(a[mt][0], a[mt][1], a[mt][2], a[mt][3], sA + offa);
            }
#pragma unroll
            for (int mt = 0; mt < 2; mt++) {
#pragma unroll
                for (int nt = 0; nt < 2; nt++) {
                    mma_f16(acc[mt][nt], a[mt], bf[nt]);
                }
            }
        }
        __syncthreads();
    }

    const int g = lane >> 2;
    const int tg2 = (lane & 3) * 2;
    float* P = g_part + (size_t)blockIdx.y * 16384;
#pragma unroll
    for (int mt = 0; mt < 2; mt++) {
        int r = mt * 16 + g;
#pragma unroll
        for (int nt = 0; nt < 2; nt++) {
            int c = col0 + wid * 16 + nt * 8 + tg2;
            float2 o0;
            float2 o1;
            o0.x = acc[mt][nt][0];
            o0.y = acc[mt][nt][1];
            o1.x = acc[mt][nt][2];
            o1.y = acc[mt][nt][3];
            *(float2*)(P + (size_t)r * 512 + c) = o0;
            *(float2*)(P + (size_t)(r + 8) * 512 + c) = o1;
        }
    }
}

/* ------------------------------------------------------------------ */
/* Kernel: deterministic split-K reduce + bias. grid 64 x 256.         */
/* ------------------------------------------------------------------ */
__global__ __launch_bounds__(256) void reduce_kernel(float* __restrict__ out,
                                                     const float* __restrict__ bm) {
    const int idx = blockIdx.x * 256 + threadIdx.x;
    const int n = idx & 511;
    float sum = bm[n];
#pragma unroll 8
    for (int s = 0; s < KSPLIT; s++) {
        sum += g_part[(size_t)s * 16384 + idx];
    }
    out[idx] = sum;
}

/* ------------------------------------------------------------------ */
extern "C" void kernel_launch(void* const* d_in, const int* in_sizes, int n_in,
                              void* d_out, int out_size) {
    const float* x = (const float*)d_in[0];
    const float* Wq = (const float*)d_in[1];
    const float* bq = (const float*)d_in[2];
    const float* Wk = (const float*)d_in[3];
    const float* bk = (const float*)d_in[4];
    const float* Wm = (const float*)d_in[5];
    const float* bm = (const float*)d_in[6];

    float* out = (float*)d_out;   /* [32, 512] */
    float* attn = out + 32 * 512; /* [32, 512, 512] */

    cudaFuncSetAttribute(proj_kernel, cudaFuncAttributeMaxDynamicSharedMemorySize,
                         GSMEM_BYTES);
    cudaFuncSetAttribute(scores_kernel, cudaFuncAttributeMaxDynamicSharedMemorySize,
                         GSMEM_BYTES);
    cudaFuncSetAttribute(ax_kernel, cudaFuncAttributeMaxDynamicSharedMemorySize,
                         GSMEM_BYTES);

    prep_x<<<dim3(8, 8, 32), 256>>>(x);
    prep_wt<<<dim3(8, 8, 2), 256>>>(Wq, Wk);
    proj_kernel<<<dim3(4, 128, 2), 256, GSMEM_BYTES>>>(bq, bk);
    scores_kernel<<<dim3(4, 4, 32), 256, GSMEM_BYTES>>>();
    rowsum_kernel<<<2048, 256>>>(attn);
    ax_kernel<<<dim3(4, 4, 32), 256, GSMEM_BYTES>>>();
    final_kernel<<<dim3(4, KSPLIT), 256>>>(Wm);
    reduce_kernel<<<64, 256>>>(out, bm);
}

// round 13
// speedup vs baseline: 1.0969x; 1.0219x over previous
#include <cuda_runtime.h>
#include <cuda_fp16.h>
#include <stdint.h>
#include <math.h>

/* GEMM-trio pipeline constants */
#define GBK 64             /* k per slab */
#define GASTR 72           /* padded smem stride (144 B rows, 16B aligned) */
#define GNITER 8           /* K=512 / GBK */
#define GSTAGES 3

/* final kernel constants */
#define FBK 32
#define FASTR 40
#define KSPLIT 64
#define KCHUNK 4096
#define BN_LD 136

/* Scratch: __device__ globals (allocation-free rule) */
__device__ uint16_t xd16[32 * 512 * 512];   /* x direct fp16 [b*512+n][h] */
__device__ uint16_t xt16[32 * 512 * 512];   /* x^T fp16 [b][h][m] */
__device__ uint16_t wt16[2 * 512 * 512];    /* Wq^T, Wk^T fp16 [z][n][k] */
__device__ uint16_t q16[32 * 512 * 512];    /* q fp16 */
__device__ uint16_t k16[32 * 512 * 512];    /* k fp16 */
__device__ uint16_t at16[32 * 512 * 512];   /* exp(sigmoid(scores)) fp16 */
__device__ uint16_t ax16[32 * 512 * 512];   /* softmax @ x, fp16 */
__device__ float g_rinv[32 * 512];          /* per-row 1/sum(exp) */
__device__ float g_part[KSPLIT * 32 * 512];

/* ------------------------------------------------------------------ */
/* Helpers                                                             */
/* ------------------------------------------------------------------ */
__device__ __forceinline__ uint32_t sptr(const void* p) {
    return (uint32_t)__cvta_generic_to_shared(p);
}

__device__ __forceinline__ void ldsm_x4(uint32_t& r0, uint32_t& r1,
                                        uint32_t& r2, uint32_t& r3,
                                        uint32_t addr) {
    asm volatile("ldmatrix.sync.aligned.m8n8.x4.shared.b16 {%0,%1,%2,%3}, [%4];"
                 : "=r"(r0), "=r"(r1), "=r"(r2), "=r"(r3)
                 : "r"(addr));
}

__device__ __forceinline__ void ldsm_x4_trans(uint32_t& r0, uint32_t& r1,
                                              uint32_t& r2, uint32_t& r3,
                                              uint32_t addr) {
    asm volatile("ldmatrix.sync.aligned.m8n8.x4.trans.shared.b16 {%0,%1,%2,%3}, [%4];"
                 : "=r"(r0), "=r"(r1), "=r"(r2), "=r"(r3)
                 : "r"(addr));
}

__device__ __forceinline__ void mma_f16(float* c, const uint32_t* a,
                                        const uint32_t* b) {
    asm volatile(
        "mma.sync.aligned.m16n8k16.row.col.f32.f16.f16.f32 "
        "{%0,%1,%2,%3}, {%4,%5,%6,%7}, {%8,%9}, {%0,%1,%2,%3};"
        : "+f"(c[0]), "+f"(c[1]), "+f"(c[2]), "+f"(c[3])
        : "r"(a[0]), "r"(a[1]), "r"(a[2]), "r"(a[3]),
          "r"(b[0]), "r"(b[1]));
}

__device__ __forceinline__ void cpa16(uint32_t dst, const void* src) {
    asm volatile("cp.async.cg.shared.global [%0], [%1], 16;"
                 :: "r"(dst), "l"(src) : "memory");
}
__device__ __forceinline__ void cpa_commit() {
    asm volatile("cp.async.commit_group;" ::: "memory");
}
template <int N>
__device__ __forceinline__ void cpa_wait() {
    asm volatile("cp.async.wait_group %0;" :: "n"(N) : "memory");
}

__device__ __forceinline__ uint16_t h1(float v) {
    __half h = __float2half_rn(v);
    return *reinterpret_cast<uint16_t*>(&h);
}

__device__ __forceinline__ void pack8_plain(const float* v, uint4& u) {
    uint16_t h[8];
#pragma unroll
    for (int j = 0; j < 8; j++) {
        h[j] = h1(v[j]);
    }
    u.x = (uint32_t)h[0] | ((uint32_t)h[1] << 16);
    u.y = (uint32_t)h[2] | ((uint32_t)h[3] << 16);
    u.z = (uint32_t)h[4] | ((uint32_t)h[5] << 16);
    u.w = (uint32_t)h[6] | ((uint32_t)h[7] << 16);
}

/* ------------------------------------------------------------------ */
/* Compute: one GBK=64 slab, 128x128 CTA tile, 16 warps (wm 4 x wn 4), */
/* warp tile 32x32, acc[2][4][4] = 32 regs.                            */
/* ------------------------------------------------------------------ */
__device__ __forceinline__ void compute128_h(uint32_t sA, uint32_t sB,
                                             int wm, int wn, int lane,
                                             float acc[2][4][4]) {
    const int lr = (lane & 7) + ((lane >> 3) & 1) * 8;
    const int lc = (lane >> 4) * 8;

#pragma unroll
    for (int h = 0; h < 4; h++) {
        uint32_t b[4][2];
#pragma unroll
        for (int p = 0; p < 2; p++) {
            uint32_t off = (uint32_t)(((wn * 32 + p * 16 + lr) * GASTR + h * 16 + lc) * 2);
            uint32_t r0, r1, r2, r3;
            ldsm_x4(r0, r1, r2, r3, sB + off);
            b[2 * p][0] = r0;
            b[2 * p][1] = r2;
            b[2 * p + 1][0] = r1;
            b[2 * p + 1][1] = r3;
        }
        uint32_t a[2][4];
#pragma unroll
        for (int mt = 0; mt < 2; mt++) {
            uint32_t off = (uint32_t)(((wm * 32 + mt * 16 + lr) * GASTR + h * 16 + lc) * 2);
            ldsm_x4(a[mt][0], a[mt][1], a[mt][2], a[mt][3], sA + off);
        }
#pragma unroll
        for (int mt = 0; mt < 2; mt++) {
#pragma unroll
            for (int nt = 0; nt < 4; nt++) {
                mma_f16(acc[mt][nt], a[mt], b[nt]);
            }
        }
    }
}

/* ------------------------------------------------------------------ */
/* Prep 1: x -> direct fp16 (xd16) AND transposed fp16 (xt16).         */
/* ------------------------------------------------------------------ */
__global__ __launch_bounds__(256) void prep_x(const float* __restrict__ x) {
    __shared__ float ts[64][65];
    const int tid = threadIdx.x;
    const int m0 = blockIdx.y * 64;
    const int h0 = blockIdx.x * 64;
    const size_t off = (size_t)blockIdx.z * 262144;
    const float* src = x + off + (size_t)m0 * 512 + h0;

#pragma unroll
    for (int i = 0; i < 4; i++) {
        int lin = i * 256 + tid;
        int r = lin >> 4;
        int c4 = (lin & 15) * 4;
        float4 v = *(const float4*)(src + (size_t)r * 512 + c4);
        ts[r][c4 + 0] = v.x;
        ts[r][c4 + 1] = v.y;
        ts[r][c4 + 2] = v.z;
        ts[r][c4 + 3] = v.w;
    }
    __syncthreads();

#pragma unroll
    for (int i = 0; i < 2; i++) {
        int lin = i * 256 + tid;
        int r = lin >> 3;
        int c8 = (lin & 7) * 8;
        float v[8];
#pragma unroll
        for (int j = 0; j < 8; j++) {
            v[j] = ts[r][c8 + j];
        }
        uint4 u;
        pack8_plain(v, u);
        *(uint4*)(xd16 + off + (size_t)(m0 + r) * 512 + h0 + c8) = u;
    }
#pragma unroll
    for (int i = 0; i < 2; i++) {
        int lin = i * 256 + tid;
        int hr = lin >> 3;
        int m8 = (lin & 7) * 8;
        float v[8];
#pragma unroll
        for (int j = 0; j < 8; j++) {
            v[j] = ts[m8 + j][hr];
        }
        uint4 u;
        pack8_plain(v, u);
        *(uint4*)(xt16 + off + (size_t)(h0 + hr) * 512 + m0 + m8) = u;
    }
}

/* ------------------------------------------------------------------ */
/* Prep 2: Wq/Wk -> transposed plain fp16 (wt16). grid (8,8,2).        */
/* ------------------------------------------------------------------ */
__global__ __launch_bounds__(256) void prep_wt(const float* __restrict__ Wq,
                                               const float* __restrict__ Wk) {
    __shared__ float ts[64][65];
    const int tid = threadIdx.x;
    const int k0 = blockIdx.y * 64;
    const int n0 = blockIdx.x * 64;
    const float* src = (blockIdx.z ? Wk : Wq) + (size_t)k0 * 512 + n0;
    const size_t dstoff = (size_t)blockIdx.z * 262144;

#pragma unroll
    for (int i = 0; i < 4; i++) {
        int lin = i * 256 + tid;
        int r = lin >> 4;
        int c4 = (lin & 15) * 4;
        float4 v = *(const float4*)(src + (size_t)r * 512 + c4);
        ts[r][c4 + 0] = v.x;
        ts[r][c4 + 1] = v.y;
        ts[r][c4 + 2] = v.z;
        ts[r][c4 + 3] = v.w;
    }
    __syncthreads();

#pragma unroll
    for (int i = 0; i < 2; i++) {
        int lin = i * 256 + tid;
        int nr = lin >> 3;
        int k8 = (lin & 7) * 8;
        float v[8];
#pragma unroll
        for (int j = 0; j < 8; j++) {
            v[j] = ts[k8 + j][nr];
        }
        uint4 u;
        pack8_plain(v, u);
        *(uint4*)(wt16 + dstoff + (size_t)(n0 + nr) * 512 + k0 + k8) = u;
    }
}

/* ------------------------------------------------------------------ */
/* Generic plain-fp16 GEMM body: 3-stage cp.async pipeline, GBK=64,    */
/* 512 threads. Pointer-increment addressing.                          */
/* ------------------------------------------------------------------ */
#define PTILE (128 * GASTR)                  /* elems per array */
#define STAGE_BYTES (2 * PTILE * 2)          /* 36864 */
#define GSMEM_BYTES (GSTAGES * STAGE_BYTES)  /* 110592 */

__device__ __forceinline__ void gemm128_body(
    const uint16_t* __restrict__ A, const uint16_t* __restrict__ B,
    uint32_t s0, int tid, int wm, int wn, int lane, float acc[2][4][4]) {
    /* 512-thread loader: rows tid>>3 and +64, col (tid&7)*8 */
    const int trow = tid >> 3;
    const int tcol = (tid & 7) * 8;
    const uint16_t* pa = A + (size_t)trow * 512 + tcol;
    const uint16_t* pb = B + (size_t)trow * 512 + tcol;
    const uint32_t soff = (uint32_t)(trow * GASTR + tcol) * 2;

#pragma unroll
    for (int s = 0; s < GSTAGES - 1; s++) {
        uint32_t sb = s0 + s * STAGE_BYTES + soff;
#pragma unroll
        for (int i = 0; i < 2; i++) {
            cpa16(sb + i * (64 * GASTR * 2), pa + i * (64 * 512));
            cpa16(sb + PTILE * 2 + i * (64 * GASTR * 2), pb + i * (64 * 512));
        }
        cpa_commit();
        pa += GBK;
        pb += GBK;
    }

    int cur = 0;      /* stage index of slab c */
    int nxt = 2;      /* stage index of slab c+2 */
    for (int c = 0; c < GNITER; c++) {
        cpa_wait<1>();
        __syncthreads();
        if (c + GSTAGES - 1 < GNITER) {
            uint32_t sb = s0 + nxt * STAGE_BYTES + soff;
#pragma unroll
            for (int i = 0; i < 2; i++) {
                cpa16(sb + i * (64 * GASTR * 2), pa + i * (64 * 512));
                cpa16(sb + PTILE * 2 + i * (64 * GASTR * 2), pb + i * (64 * 512));
            }
            pa += GBK;
            pb += GBK;
        }
        cpa_commit();   /* unconditional: keeps group count in lockstep */
        uint32_t sb = s0 + cur * STAGE_BYTES;
        compute128_h(sb, sb + PTILE * 2, wm, wn, lane, acc);
        cur = (cur == 2) ? 0 : cur + 1;
        nxt = (nxt == 2) ? 0 : nxt + 1;
    }
}

/* ------------------------------------------------------------------ */
/* Kernel: q/k projections. grid (4, 128, 2), 512 thr, 2 CTAs/SM.      */
/* ------------------------------------------------------------------ */
__global__ __launch_bounds__(512, 2) void proj_kernel(
    const float* __restrict__ bq, const float* __restrict__ bk) {
    extern __shared__ uint16_t dynsm[];

    const int tid = threadIdx.x;
    const int lane = tid & 31;
    const int wid = tid >> 5;
    const int wm = wid & 3;
    const int wn = wid >> 2;
    const int z = blockIdx.z;
    const int row0 = blockIdx.y * 128;
    const int col0 = blockIdx.x * 128;

    const uint16_t* A = xd16 + (size_t)row0 * 512;
    const uint16_t* B = wt16 + (size_t)z * 262144 + (size_t)col0 * 512;

    float acc[2][4][4] = {};
    gemm128_body(A, B, sptr(dynsm), tid, wm, wn, lane, acc);

    const float* bias = z ? bk : bq;
    uint16_t* O = z ? k16 : q16;
    const int g = lane >> 2;
    const int tg2 = (lane & 3) * 2;
#pragma unroll
    for (int mt = 0; mt < 2; mt++) {
        int r = row0 + wm * 32 + mt * 16 + g;
#pragma unroll
        for (int nt = 0; nt < 4; nt++) {
            int c = col0 + wn * 32 + nt * 8 + tg2;
            float2 bv = *(const float2*)(bias + c);
            __half2 p0 = __floats2half2_rn(acc[mt][nt][0] + bv.x, acc[mt][nt][1] + bv.y);
            __half2 p1 = __floats2half2_rn(acc[mt][nt][2] + bv.x, acc[mt][nt][3] + bv.y);
            *(uint32_t*)(O + (size_t)r * 512 + c) = *reinterpret_cast<uint32_t*>(&p0);
            *(uint32_t*)(O + (size_t)(r + 8) * 512 + c) = *reinterpret_cast<uint32_t*>(&p1);
        }
    }
}

/* ------------------------------------------------------------------ */
/* Kernel: scores -> at16 = exp(sigmoid(q k^T / sqrt(512))) fp16.      */
/* Fast-math epilogue. grid (4,4,32), 512 thr.                         */
/* ------------------------------------------------------------------ */
__device__ __forceinline__ float esig(float x, float scale) {
    return __expf(__fdividef(1.f, 1.f + __expf(-x * scale)));
}

__global__ __launch_bounds__(512, 2) void scores_kernel() {
    extern __shared__ uint16_t dynsm[];

    const int tid = threadIdx.x;
    const int lane = tid & 31;
    const int wid = tid >> 5;
    const int wm = wid & 3;
    const int wn = wid >> 2;
    const int b = blockIdx.z;
    const int row0 = blockIdx.y * 128;
    const int col0 = blockIdx.x * 128;

    const uint16_t* A = q16 + ((size_t)b * 512 + row0) * 512;
    const uint16_t* B = k16 + ((size_t)b * 512 + col0) * 512;

    float acc[2][4][4] = {};
    gemm128_body(A, B, sptr(dynsm), tid, wm, wn, lane, acc);

    const float scale = 0.04419417382415922f; /* 1/sqrt(512) */
    uint16_t* E = at16 + (size_t)b * 262144;
    const int g = lane >> 2;
    const int tg2 = (lane & 3) * 2;
#pragma unroll
    for (int mt = 0; mt < 2; mt++) {
        int r = row0 + wm * 32 + mt * 16 + g;
#pragma unroll
        for (int nt = 0; nt < 4; nt++) {
            int c = col0 + wn * 32 + nt * 8 + tg2;
            __half2 p0 = __floats2half2_rn(esig(acc[mt][nt][0], scale),
                                           esig(acc[mt][nt][1], scale));
            __half2 p1 = __floats2half2_rn(esig(acc[mt][nt][2], scale),
                                           esig(acc[mt][nt][3], scale));
            *(uint32_t*)(E + (size_t)r * 512 + c) = *reinterpret_cast<uint32_t*>(&p0);
            *(uint32_t*)(E + (size_t)(r + 8) * 512 + c) = *reinterpret_cast<uint32_t*>(&p1);
        }
    }
}

/* ------------------------------------------------------------------ */
/* Kernel: warp-per-row rowsum. Reads at16, writes normalized fp32     */
/* attn and g_rinv. grid 2048 x 256.                                   */
/* ------------------------------------------------------------------ */
__global__ __launch_bounds__(256) void rowsum_kernel(float* __restrict__ attn) {
    const int w = threadIdx.x >> 5;
    const int lane = threadIdx.x & 31;
    const size_t row = (size_t)blockIdx.x * 8 + w;
    const size_t base = row * 512;

    uint2 u[4];
#pragma unroll
    for (int i = 0; i < 4; i++) {
        u[i] = *(const uint2*)(at16 + base + i * 128 + lane * 4);
    }
    float e[16];
    float s = 0.f;
#pragma unroll
    for (int i = 0; i < 4; i++) {
        __half2 h0 = *reinterpret_cast<__half2*>(&u[i].x);
        __half2 h1v = *reinterpret_cast<__half2*>(&u[i].y);
        float2 f0 = __half22float2(h0);
        float2 f1 = __half22float2(h1v);
        e[i * 4 + 0] = f0.x;
        e[i * 4 + 1] = f0.y;
        e[i * 4 + 2] = f1.x;
        e[i * 4 + 3] = f1.y;
        s += f0.x + f0.y + f1.x + f1.y;
    }
#pragma unroll
    for (int o = 16; o > 0; o >>= 1) {
        s += __shfl_xor_sync(0xffffffffu, s, o);
    }
    const float inv = 1.f / s;
    if (lane == 0) {
        g_rinv[row] = inv;
    }
#pragma unroll
    for (int i = 0; i < 4; i++) {
        float4 o;
        o.x = e[i * 4 + 0] * inv;
        o.y = e[i * 4 + 1] * inv;
        o.z = e[i * 4 + 2] * inv;
        o.w = e[i * 4 + 3] * inv;
        *(float4*)(attn + base + i * 128 + lane * 4) = o;
    }
}

/* ------------------------------------------------------------------ */
/* Kernel: ax = softmax @ x via exp-A GEMM + per-row 1/sum epilogue.   */
/* grid (4,4,32), 512 thr.                                             */
/* ------------------------------------------------------------------ */
__global__ __launch_bounds__(512, 2) void ax_kernel() {
    extern __shared__ uint16_t dynsm[];

    const int tid = threadIdx.x;
    const int lane = tid & 31;
    const int wid = tid >> 5;
    const int wm = wid & 3;
    const int wn = wid >> 2;
    const int b = blockIdx.z;
    const int row0 = blockIdx.y * 128;
    const int col0 = blockIdx.x * 128;

    const uint16_t* A = at16 + ((size_t)b * 512 + row0) * 512;
    const uint16_t* B = xt16 + ((size_t)b * 512 + col0) * 512;

    float acc[2][4][4] = {};
    gemm128_body(A, B, sptr(dynsm), tid, wm, wn, lane, acc);

    const size_t rowg = (size_t)b * 512;
    const int g = lane >> 2;
    const int tg2 = (lane & 3) * 2;
#pragma unroll
    for (int mt = 0; mt < 2; mt++) {
        int r = row0 + wm * 32 + mt * 16 + g;
        float i0 = g_rinv[rowg + r];
        float i1 = g_rinv[rowg + r + 8];
#pragma unroll
        for (int nt = 0; nt < 4; nt++) {
            int c = col0 + wn * 32 + nt * 8 + tg2;
            __half2 p0 = __floats2half2_rn(acc[mt][nt][0] * i0, acc[mt][nt][1] * i0);
            __half2 p1 = __floats2half2_rn(acc[mt][nt][2] * i1, acc[mt][nt][3] * i1);
            *(uint32_t*)(ax16 + (rowg + r) * 512 + c) = *reinterpret_cast<uint32_t*>(&p0);
            *(uint32_t*)(ax16 + (rowg + r + 8) * 512 + c) = *reinterpret_cast<uint32_t*>(&p1);
        }
    }
}

/* ------------------------------------------------------------------ */
/* Kernel: split-K partials of out = ax.reshape(32,262144) @ Wm.       */
/* (unchanged — measured at the LTS bandwidth cap)                     */
/* ------------------------------------------------------------------ */
#define FAEL (32 * FASTR)              /* A stage elems: [m][k] */
#define FBEL (32 * BN_LD)              /* B stage elems: [k][n] */
#define FSTAGE (FAEL + FBEL)

__global__ __launch_bounds__(256, 2) void final_kernel(const float* __restrict__ Wm) {
    __shared__ alignas(16) uint16_t dsm[2 * FSTAGE];

    const int tid = threadIdx.x;
    const int lane = tid & 31;
    const int wid = tid >> 5;
    const int col0 = blockIdx.x * 128;
    const size_t kbase = (size_t)blockIdx.y * KCHUNK;

    float acc[2][2][4] = {};
    uint2 va;
    float4 vb[4];
    const int am = tid >> 3;
    const int ak = (tid & 7) * 4;
    const int bk_r = tid >> 5;
    const int bn4 = (tid & 31) * 4;

    va = *(const uint2*)(ax16 + (size_t)am * 262144 + kbase + ak);
#pragma unroll
    for (int i = 0; i < 4; i++) {
        vb[i] = *(const float4*)(Wm + (kbase + bk_r + i * 8) * 512 + col0 + bn4);
    }

    auto store_stage = [&](uint16_t* stg) {
        *(uint2*)(stg + am * FASTR + ak) = va;
        uint16_t* bs = stg + FAEL;
#pragma unroll
        for (int i = 0; i < 4; i++) {
            __half2 p0 = __floats2half2_rn(vb[i].x, vb[i].y);
            __half2 p1 = __floats2half2_rn(vb[i].z, vb[i].w);
            uint2 u;
            u.x = *reinterpret_cast<uint32_t*>(&p0);
            u.y = *reinterpret_cast<uint32_t*>(&p1);
            *(uint2*)(bs + (bk_r + i * 8) * BN_LD + bn4) = u;
        }
    };

    store_stage(dsm);
    va = *(const uint2*)(ax16 + (size_t)am * 262144 + kbase + FBK + ak);
#pragma unroll
    for (int i = 0; i < 4; i++) {
        vb[i] = *(const float4*)(Wm + (kbase + FBK + bk_r + i * 8) * 512 + col0 + bn4);
    }
    __syncthreads();

    const int lr = (lane & 7) + ((lane >> 3) & 1) * 8;
    const int lc = (lane >> 4) * 8;
    const int trow = (lane >> 4) * 8 + (lane & 7);
    const int tcol = ((lane >> 3) & 1) * 8;

    for (int k0 = 0; k0 < KCHUNK; k0 += FBK) {
        int cur = (k0 >> 5) & 1;
        if (k0 + FBK < KCHUNK) {
            store_stage(dsm + (cur ^ 1) * FSTAGE);
        }
        if (k0 + 2 * FBK < KCHUNK) {
            va = *(const uint2*)(ax16 + (size_t)am * 262144 + kbase + k0 + 2 * FBK + ak);
#pragma unroll
            for (int i = 0; i < 4; i++) {
                vb[i] = *(const float4*)(Wm + (kbase + k0 + 2 * FBK + bk_r + i * 8) * 512 +
                                         col0 + bn4);
            }
        }
        uint32_t base = sptr(dsm) + cur * FSTAGE * 2;
        uint32_t sA = base;
        uint32_t sB = base + FAEL * 2;
#pragma unroll
        for (int ks = 0; ks < FBK; ks += 16) {
            uint32_t bf[2][2];
            uint32_t offb = (uint32_t)(((ks + trow) * BN_LD + wid * 16 + tcol) * 2);
            uint32_t r0, r1, r2, r3;
            ldsm_x4_trans(r0, r1, r2, r3, sB + offb);
            bf[0][0] = r0;
            bf[1][0] = r1;
            bf[0][1] = r2;
            bf[1][1] = r3;
            uint32_t a[2][4];
#pragma unroll
            for (int mt = 0; mt < 2; mt++) {
                uint32_t offa = (uint32_t)(((mt * 16 + lr) * FASTR + ks + lc) * 2);
                ldsm_x4(a[mt][0], a[mt][1], a[mt][2], a[mt][3], sA + offa);
            }
#pragma unroll
            for (int mt = 0; mt < 2; mt++) {
#pragma unroll
                for (int nt = 0; nt < 2; nt++) {
                    mma_f16(acc[mt][nt], a[mt], bf[nt]);
                }
            }
        }
        __syncthreads();
    }

    const int g = lane >> 2;
    const int tg2 = (lane & 3) * 2;
    float* P = g_part + (size_t)blockIdx.y * 16384;
#pragma unroll
    for (int mt = 0; mt < 2; mt++) {
        int r = mt * 16 + g;
#pragma unroll
        for (int nt = 0; nt < 2; nt++) {
            int c = col0 + wid * 16 + nt * 8 + tg2;
            float2 o0;
            float2 o1;
            o0.x = acc[mt][nt][0];
            o0.y = acc[mt][nt][1];
            o1.x = acc[mt][nt][2];
            o1.y = acc[mt][nt][3];
            *(float2*)(P + (size_t)r * 512 + c) = o0;
            *(float2*)(P + (size_t)(r + 8) * 512 + c) = o1;
        }
    }
}

/* ------------------------------------------------------------------ */
/* Kernel: deterministic split-K reduce + bias. grid 64 x 256.         */
/* ------------------------------------------------------------------ */
__global__ __launch_bounds__(256) void reduce_kernel(float* __restrict__ out,
                                                     const float* __restrict__ bm) {
    const int idx = blockIdx.x * 256 + threadIdx.x;
    const int n = idx & 511;
    float sum = bm[n];
#pragma unroll 8
    for (int s = 0; s < KSPLIT; s++) {
        sum += g_part[(size_t)s * 16384 + idx];
    }
    out[idx] = sum;
}

/* ------------------------------------------------------------------ */
extern "C" void kernel_launch(void* const* d_in, const int* in_sizes, int n_in,
                              void* d_out, int out_size) {
    const float* x = (const float*)d_in[0];
    const float* Wq = (const float*)d_in[1];
    const float* bq = (const float*)d_in[2];
    const float* Wk = (const float*)d_in[3];
    const float* bk = (const float*)d_in[4];
    const float* Wm = (const float*)d_in[5];
    const float* bm = (const float*)d_in[6];

    float* out = (float*)d_out;   /* [32, 512] */
    float* attn = out + 32 * 512; /* [32, 512, 512] */

    cudaFuncSetAttribute(proj_kernel, cudaFuncAttributeMaxDynamicSharedMemorySize,
                         GSMEM_BYTES);
    cudaFuncSetAttribute(scores_kernel, cudaFuncAttributeMaxDynamicSharedMemorySize,
                         GSMEM_BYTES);
    cudaFuncSetAttribute(ax_kernel, cudaFuncAttributeMaxDynamicSharedMemorySize,
                         GSMEM_BYTES);

    prep_x<<<dim3(8, 8, 32), 256>>>(x);
    prep_wt<<<dim3(8, 8, 2), 256>>>(Wq, Wk);
    proj_kernel<<<dim3(4, 128, 2), 512, GSMEM_BYTES>>>(bq, bk);
    scores_kernel<<<dim3(4, 4, 32), 512, GSMEM_BYTES>>>();
    rowsum_kernel<<<2048, 256>>>(attn);
    ax_kernel<<<dim3(4, 4, 32), 512, GSMEM_BYTES>>>();
    final_kernel<<<dim3(4, KSPLIT), 256>>>(Wm);
    reduce_kernel<<<64, 256>>>(out, bm);
}